// round 7
// baseline (speedup 1.0000x reference)
#include <cuda_runtime.h>
#include <cuda_bf16.h>
#include <math.h>
#include <cstdint>

#define I_ 16
#define T_ 64
#define Q_ 196
#define K_ 32
#define E_ 512
#define H_ 8
#define D_ 64

#define OUT_N   (I_*T_*E_)                  // 524288
#define ATT_N   (I_*T_*H_*Q_*K_)            // 51380224
#define SCALE_  0.044194173824159216f       // 1/sqrt(512)
#define LOG2E_  1.4426950408889634f
#define SC2_    (SCALE_*LOG2E_)

#define SA_  200                            // A/B smem stride (bf16 elems), padded
#define MR_  208                            // A rows (196 padded to 13*16)
#define EST_ 36                             // sE row stride (floats)

#define ABYTES   (MR_*SA_*2)                // 83200 (also holds sE: 208*36*4=29952)
#define BBUF     (K_*SA_*2)                 // 12800
#define B_OFF    ABYTES                     // 83200
#define V_OFF    (B_OFF + 2*BBUF)           // 108800
#define RINV_OFF (V_OFF + 2*K_*D_*4)        // 125184
#define MK_OFF   (RINV_OFF + MR_*4)         // 126016
#define CA_OFF   (MK_OFF + 256)             // 126272
#define TA_OFF   (CA_OFF + 128)             // 126400
#define TB_OFF   (TA_OFF + 128)             // 126528
#define SMEM_ATTN (TB_OFF + 128)            // 126656

// -------- scratch (device globals: no allocations allowed) --------
__device__ float g_query[I_*H_*Q_*D_];   // (i,h,q,d)
__device__ float g_key  [T_*H_*K_*D_];   // (t,h,k,d)
__device__ float g_value[T_*H_*K_*D_];   // (t,h,k,d)
__device__ float g_pooled[I_*T_*E_];     // (i*T+t, e)
__device__ float g_maskf[T_*K_];
__device__ unsigned char g_kb[(size_t)T_*H_*BBUF];   // pre-split bf16 B tiles [hi|lo|hi]

// -------- PTX helpers (sm_80-class, safe on plain sm_103 target) --------
__device__ __forceinline__ unsigned smem_u32(const void* p) {
    unsigned a;
    asm("{ .reg .u64 t; cvta.to.shared.u64 t, %1; cvt.u32.u64 %0, t; }" : "=r"(a) : "l"(p));
    return a;
}
__device__ __forceinline__ float ex2(float x) {          // single MUFU, no libm expansion
    float y;
    asm("ex2.approx.f32 %0, %1;" : "=f"(y) : "f"(x));
    return y;
}
__device__ __forceinline__ void ldm_x4(unsigned addr, unsigned& r0, unsigned& r1,
                                       unsigned& r2, unsigned& r3) {
    asm volatile("ldmatrix.sync.aligned.m8n8.x4.shared.b16 {%0,%1,%2,%3}, [%4];"
                 : "=r"(r0), "=r"(r1), "=r"(r2), "=r"(r3) : "r"(addr));
}
__device__ __forceinline__ void ldm_x2(unsigned addr, unsigned& r0, unsigned& r1) {
    asm volatile("ldmatrix.sync.aligned.m8n8.x2.shared.b16 {%0,%1}, [%2];"
                 : "=r"(r0), "=r"(r1) : "r"(addr));
}
__device__ __forceinline__ void mma_bf16(float* c, unsigned a0, unsigned a1, unsigned a2,
                                         unsigned a3, unsigned b0, unsigned b1) {
    asm volatile("mma.sync.aligned.m16n8k16.row.col.f32.bf16.bf16.f32 "
                 "{%0,%1,%2,%3}, {%4,%5,%6,%7}, {%8,%9}, {%0,%1,%2,%3};"
                 : "+f"(c[0]), "+f"(c[1]), "+f"(c[2]), "+f"(c[3])
                 : "r"(a0), "r"(a1), "r"(a2), "r"(a3), "r"(b0), "r"(b1));
}

// -------- dummy (ncu launch-slot alignment: attn lands on skip-5 capture) --------
__global__ void dummy_kernel() {}

// -------- mask conversion (robust to bool/int32/float32 serialization) --------
__global__ void mask_kernel(const void* mp) {
    __shared__ int mode;
    if (threadIdx.x == 0) {
        const unsigned char* b = (const unsigned char*)mp;
        int c3f = 0, cnz = 0;
        for (int k = 0; k < 512; k++) {
            if (b[4*k+3] == 0x3F) c3f++;
            if (b[4*k+1] | b[4*k+2]) cnz++;
        }
        mode = (c3f > 8) ? 2 : ((cnz > 8) ? 0 : 1);
    }
    __syncthreads();
    int m = mode;
    for (int idx = threadIdx.x; idx < T_*K_; idx += blockDim.x) {
        float v;
        if (m == 0)      v = ((const unsigned char*)mp)[idx] ? 1.f : 0.f;
        else if (m == 1) v = ((const int*)mp)[idx] ? 1.f : 0.f;
        else             v = (((const float*)mp)[idx] != 0.f) ? 1.f : 0.f;
        g_maskf[idx] = v;
    }
}

// -------- fused Q/K/V projections, one launch (904 CTAs) --------
__global__ void proj_all(const float* __restrict__ image, const float* __restrict__ text,
                         const float* __restrict__ Wq, const float* __restrict__ Wk,
                         const float* __restrict__ Wv) {
    __shared__ float sA[64*33];
    __shared__ float sB[64*33];
    int bid = blockIdx.x;
    int which, h, rb;
    const float *X, *W;
    float* Y;
    if (bid < 392)      { which = 0; h = bid/49;        rb = bid%49;        X = image; W = Wq; Y = g_query; }
    else if (bid < 648) { which = 1; h = (bid-392)/32;  rb = (bid-392)%32;  X = text;  W = Wk; Y = g_key;   }
    else                { which = 2; h = (bid-648)/32;  rb = (bid-648)%32;  X = text;  W = Wv; Y = g_value; }
    int r0 = rb * 64;
    int tid = threadIdx.x;
    int tx = tid & 15, ty = tid >> 4;
    float acc[4][4] = {};

    #pragma unroll
    for (int kc = 0; kc < 64; kc += 32) {
        for (int idx = tid; idx < 2048; idx += 256) {
            int r = idx >> 5, kk = idx & 31;
            sA[r*33 + kk] = X[(r0 + r)*E_ + h*64 + kc + kk];
            sB[r*33 + kk] = W[r*64 + kc + kk];
        }
        __syncthreads();
        #pragma unroll
        for (int kk = 0; kk < 32; kk++) {
            float a[4], b[4];
            #pragma unroll
            for (int r = 0; r < 4; r++) a[r] = sA[(ty*4 + r)*33 + kk];
            #pragma unroll
            for (int c = 0; c < 4; c++) b[c] = sB[(tx*4 + c)*33 + kk];
            #pragma unroll
            for (int r = 0; r < 4; r++)
                #pragma unroll
                for (int c = 0; c < 4; c++) acc[r][c] += a[r] * b[c];
        }
        __syncthreads();
    }
    #pragma unroll
    for (int r = 0; r < 4; r++) {
        int row = r0 + ty*4 + r;
        long long obase;
        if (which == 0) { int i = row / Q_, q = row % Q_;  obase = ((long long)(i*H_ + h)*Q_ + q)*64; }
        else            { int t = row >> 5, k = row & 31;  obase = ((long long)(t*H_ + h)*K_ + k)*64; }
        #pragma unroll
        for (int c = 0; c < 4; c++)
            Y[obase + tx*4 + c] = acc[r][c];
    }
}

// -------- one-shot K split-conversion: g_key -> g_kb bf16 [hi|lo|hi], stride SA_ --------
__global__ void kprep_kernel() {
    int th = blockIdx.x, tid = threadIdx.x;
    const float* Kg = g_key + (size_t)th*(K_*D_);
    unsigned char* B = g_kb + (size_t)th*BBUF;
    for (int idx = tid; idx < (K_*D_)/2; idx += 256) {
        int k = idx >> 5, d2 = (idx & 31)*2;
        float2 x = *(const float2*)&Kg[k*64 + d2];
        __nv_bfloat162 hi = __floats2bfloat162_rn(x.x, x.y);
        float2 hf = __bfloat1622float2(hi);
        __nv_bfloat162 lo = __floats2bfloat162_rn(x.x - hf.x, x.y - hf.y);
        *(__nv_bfloat162*)(B + (k*SA_ + d2)*2)       = hi;
        *(__nv_bfloat162*)(B + (k*SA_ + 64 + d2)*2)  = lo;
        *(__nv_bfloat162*)(B + (k*SA_ + 128 + d2)*2) = hi;
    }
}

// -------- fused warp-MMA energy + dual softmax + pooled-AV --------
// grid 128 (= i*8 + h), 256 threads, occ 1. Split bf16: A=[hi|hi|lo], B=[hi|lo|hi], K=192.
__global__ void __launch_bounds__(256, 1)
attn_kernel(float* __restrict__ out, int wAttn, int wText) {
    extern __shared__ unsigned char smem[];
    unsigned sbase = smem_u32(smem);
    float* sE    = (float*)smem;                    // overlaps A region (A consumed into regs)
    float* sV    = (float*)(smem + V_OFF);
    float* sRinv = (float*)(smem + RINV_OFF);
    float* sMkA  = (float*)(smem + MK_OFF);
    float* sCA   = (float*)(smem + CA_OFF);
    float* sTA   = (float*)(smem + TA_OFF);
    float* sTB   = (float*)(smem + TB_OFF);

    int ih = blockIdx.x;
    int h = ih & 7, i = ih >> 3;
    int tid = threadIdx.x, lane = tid & 31, wid = tid >> 5;

    // ---- stage A (Q tile) as bf16 split into padded smem ----
    {
        unsigned* z = (unsigned*)smem;
        for (int idx = tid; idx < (MR_*SA_)/2; idx += 256) z[idx] = 0u;
        __syncthreads();
        const float* Qg = g_query + (size_t)ih*(Q_*D_);
        unsigned char* A = smem;
        for (int idx = tid; idx < (Q_*D_)/2; idx += 256) {
            int q = idx >> 5, d2 = (idx & 31)*2;
            float2 x = *(const float2*)&Qg[q*64 + d2];
            __nv_bfloat162 hi = __floats2bfloat162_rn(x.x, x.y);
            float2 hf = __bfloat1622float2(hi);
            __nv_bfloat162 lo = __floats2bfloat162_rn(x.x - hf.x, x.y - hf.y);
            *(__nv_bfloat162*)(A + (q*SA_ + d2)*2)       = hi;
            *(__nv_bfloat162*)(A + (q*SA_ + 64 + d2)*2)  = hi;
            *(__nv_bfloat162*)(A + (q*SA_ + 128 + d2)*2) = lo;
        }
        __syncthreads();
    }

    // ---- hoist A fragments into registers (reused for all 64 t-tiles) ----
    unsigned af[2][12][4];
    bool has2 = (wid + 8) < 13;
    {
        int lrow = lane & 15;
        int lcol = (lane < 16) ? 0 : 8;
        #pragma unroll
        for (int wti = 0; wti < 2; wti++) {
            int wt = wid + wti*8;
            if (wti == 0 || has2) {
                #pragma unroll
                for (int ks = 0; ks < 12; ks++) {
                    unsigned addr = sbase + (unsigned)(((wt*16 + lrow)*SA_ + ks*16 + lcol)*2);
                    ldm_x4(addr, af[wti][ks][0], af[wti][ks][1], af[wti][ks][2], af[wti][ks][3]);
                }
            }
        }
    }

    // ---- stage t=0 K/V/mask into buffer 0 (pure copies; K pre-split in g_kb) ----
    {
        const float4* bs = (const float4*)(g_kb + (size_t)(0*H_ + h)*BBUF);
        float4* bd = (float4*)(smem + B_OFF);
        for (int idx = tid; idx < BBUF/16; idx += 256) bd[idx] = bs[idx];
        const float4* vs = (const float4*)(g_value + (size_t)(0*H_ + h)*(K_*D_));
        float4* vd = (float4*)sV;
        for (int idx = tid; idx < (K_*D_)/4; idx += 256) vd[idx] = vs[idx];
        if (tid < K_) sMkA[tid] = g_maskf[0*K_ + tid];
    }
    __syncthreads();

    int p = 0;
    for (int t = 0; t < T_; t++) {
        // ---- MMA phase: energy for tile t into sE (row-major, stride 36) ----
        {
            unsigned sBb = sbase + B_OFF + (unsigned)(p*BBUF);
            int ln = lane & 15;
            int bn = ln & 7;
            int bc = (ln < 8) ? 0 : 8;
            float c[2][4][4];
            #pragma unroll
            for (int a = 0; a < 2; a++)
                #pragma unroll
                for (int nt = 0; nt < 4; nt++)
                    #pragma unroll
                    for (int r = 0; r < 4; r++) c[a][nt][r] = 0.f;
            #pragma unroll
            for (int ks = 0; ks < 12; ks++) {
                unsigned b0[4], b1[4];
                #pragma unroll
                for (int nt = 0; nt < 4; nt++) {
                    unsigned addr = sBb + (unsigned)(((nt*8 + bn)*SA_ + ks*16 + bc)*2);
                    ldm_x2(addr, b0[nt], b1[nt]);
                }
                #pragma unroll
                for (int nt = 0; nt < 4; nt++) {
                    mma_bf16(c[0][nt], af[0][ks][0], af[0][ks][1], af[0][ks][2], af[0][ks][3],
                             b0[nt], b1[nt]);
                    if (has2)
                        mma_bf16(c[1][nt], af[1][ks][0], af[1][ks][1], af[1][ks][2], af[1][ks][3],
                                 b0[nt], b1[nt]);
                }
            }
            int g = lane >> 2, q2 = lane & 3;
            #pragma unroll
            for (int wti = 0; wti < 2; wti++) {
                if (wti == 1 && !has2) break;
                int r0 = (wid + wti*8)*16 + g;
                #pragma unroll
                for (int nt = 0; nt < 4; nt++) {
                    int col = nt*8 + 2*q2;
                    *(float2*)&sE[r0*EST_ + col]       = make_float2(c[wti][nt][0], c[wti][nt][1]);
                    *(float2*)&sE[(r0 + 8)*EST_ + col] = make_float2(c[wti][nt][2], c[wti][nt][3]);
                }
            }
        }

        // ---- prefetch tile t+1 into other buffers (overlaps tensor execution) ----
        if (t + 1 < T_) {
            int pn = p ^ 1;
            const float4* bs = (const float4*)(g_kb + (size_t)((t+1)*H_ + h)*BBUF);
            float4* bd = (float4*)(smem + B_OFF + pn*BBUF);
            for (int idx = tid; idx < BBUF/16; idx += 256) bd[idx] = bs[idx];
            const float4* vs = (const float4*)(g_value + (size_t)((t+1)*H_ + h)*(K_*D_));
            float4* vd = (float4*)(sV + pn*(K_*D_));
            for (int idx = tid; idx < (K_*D_)/4; idx += 256) vd[idx] = vs[idx];
            if (tid < K_) sMkA[pn*32 + tid] = g_maskf[(t+1)*K_ + tid];
        }
        __syncthreads();

        const float* mk = sMkA + p*32;

        // ---- exp + row sums (thread owns q-row; conflict-free float4; raw MUFU) ----
        if (tid < Q_) {
            float4* row = (float4*)(sE + tid*EST_);
            float rowsum = 0.f;
            #pragma unroll
            for (int j = 0; j < 8; j++) {
                float4 v = row[j];
                v.x = (mk[4*j + 0] != 0.f) ? ex2(v.x * SC2_) : 0.f;
                v.y = (mk[4*j + 1] != 0.f) ? ex2(v.y * SC2_) : 0.f;
                v.z = (mk[4*j + 2] != 0.f) ? ex2(v.z * SC2_) : 0.f;
                v.w = (mk[4*j + 3] != 0.f) ? ex2(v.w * SC2_) : 0.f;
                rowsum += (v.x + v.y) + (v.z + v.w);
                row[j] = v;
            }
            sRinv[tid] = 1.f / rowsum;
        }
        __syncthreads();

        // ---- column sums (8 threads per k, conflict-free) ----
        {
            int kcol = tid >> 3, qoff = tid & 7;
            float pe = 0.f, pa = 0.f;
            for (int q = qoff; q < Q_; q += 8) {
                float ee = sE[q*EST_ + kcol];
                pe += ee; pa += ee * sRinv[q];
            }
            #pragma unroll
            for (int o = 4; o > 0; o >>= 1) {
                pe += __shfl_xor_sync(0xffffffffu, pe, o);
                pa += __shfl_xor_sync(0xffffffffu, pa, o);
            }
            if (qoff == 0) {
                float m = mk[kcol];
                sCA[kcol] = pa;
                sTA[kcol] = (m != 0.f) ? (1.f / pe) : 0.f;
                sTB[kcol] = (m != 0.f) ? 0.f : (1.f / (float)Q_);
            }
        }
        __syncthreads();

        // ---- writeout (STG.128 only) + pooled ----
        long long tileOff = ((long long)(i*T_ + t)*H_ + h) * (Q_*K_);
        if (wAttn | wText) {
            float4* attn4 = (float4*)(out + OUT_N + tileOff);
            float4* text4 = (float4*)(out + OUT_N + (long long)ATT_N + tileOff);
            const float4* sE4 = (const float4*)sE;
            const float4* tA4 = (const float4*)sTA;
            const float4* tB4 = (const float4*)sTB;
            for (int idx = tid; idx < Q_*8; idx += 256) {
                int q = idx >> 3, c = idx & 7;
                float4 e4 = sE4[q*(EST_/4) + c];
                if (wAttn) {
                    float r = sRinv[q];
                    float4 a4 = { e4.x*r, e4.y*r, e4.z*r, e4.w*r };
                    attn4[idx] = a4;
                }
                if (wText) {
                    float4 ta = tA4[c], tb = tB4[c];
                    float4 x4 = { fmaf(e4.x, ta.x, tb.x), fmaf(e4.y, ta.y, tb.y),
                                  fmaf(e4.z, ta.z, tb.z), fmaf(e4.w, ta.w, tb.w) };
                    text4[idx] = x4;
                }
            }
        }
        if (tid < 64) {
            float a = 0.f;
            const float* vv = sV + p*(K_*D_);
            #pragma unroll
            for (int k = 0; k < 32; k++) a += sCA[k] * vv[k*D_ + tid];
            g_pooled[(long long)(i*T_ + t)*E_ + h*64 + tid] = a * (1.f / (float)Q_);
        }
        __syncthreads();
        p ^= 1;
    }
}

// -------- final: out[row,f] = sum_e pooled[row,e]*Wo[f,e] + bo[f] (reg-prefetched) --------
__global__ void fc_kernel(const float* __restrict__ Wo, const float* __restrict__ bo,
                          float* __restrict__ out) {
    __shared__ float sA[64*33];
    __shared__ float sB[64*33];
    int rt = blockIdx.x * 64;
    int ct = blockIdx.y * 64;
    int tid = threadIdx.x;
    int tx = tid & 15, ty = tid >> 4;
    float acc[4][4] = {};
    float ra[8], rb[8];

    #pragma unroll
    for (int j = 0; j < 8; j++) {
        int idx = tid + j*256;
        int r = idx >> 5, kk = idx & 31;
        ra[j] = g_pooled[(rt + r)*E_ + kk];
        rb[j] = Wo[(ct + r)*E_ + kk];
    }
    for (int kc = 0; kc < E_; kc += 32) {
        #pragma unroll
        for (int j = 0; j < 8; j++) {
            int idx = tid + j*256;
            int r = idx >> 5, kk = idx & 31;
            sA[r*33 + kk] = ra[j];
            sB[r*33 + kk] = rb[j];
        }
        __syncthreads();
        if (kc + 32 < E_) {
            #pragma unroll
            for (int j = 0; j < 8; j++) {
                int idx = tid + j*256;
                int r = idx >> 5, kk = idx & 31;
                ra[j] = g_pooled[(rt + r)*E_ + kc + 32 + kk];
                rb[j] = Wo[(ct + r)*E_ + kc + 32 + kk];
            }
        }
        #pragma unroll
        for (int kk = 0; kk < 32; kk++) {
            float a[4], b[4];
            #pragma unroll
            for (int r = 0; r < 4; r++) a[r] = sA[(ty*4 + r)*33 + kk];
            #pragma unroll
            for (int c = 0; c < 4; c++) b[c] = sB[(tx*4 + c)*33 + kk];
            #pragma unroll
            for (int r = 0; r < 4; r++)
                #pragma unroll
                for (int c = 0; c < 4; c++) acc[r][c] += a[r] * b[c];
        }
        __syncthreads();
    }
    #pragma unroll
    for (int r = 0; r < 4; r++)
        #pragma unroll
        for (int c = 0; c < 4; c++)
            out[(rt + ty*4 + r)*E_ + ct + tx*4 + c] = acc[r][c] + bo[ct + tx*4 + c];
}

// -------- launch --------
extern "C" void kernel_launch(void* const* d_in, const int* in_sizes, int n_in,
                              void* d_out, int out_size) {
    const float* image = (const float*)d_in[0];
    const float* text  = (const float*)d_in[1];
    const void*  mask  =                d_in[2];
    const float* Wq    = (const float*)d_in[3];
    const float* Wk    = (const float*)d_in[4];
    const float* Wv    = (const float*)d_in[5];
    const float* Wo    = (const float*)d_in[6];
    const float* bo    = (const float*)d_in[7];
    float* out = (float*)d_out;

    cudaFuncSetAttribute(attn_kernel, cudaFuncAttributeMaxDynamicSharedMemorySize, SMEM_ATTN);

    // 7 launches/call -> ncu's skip-5 capture slot (5 mod 7) is always attn_kernel
    mask_kernel<<<1, 256>>>(mask);                                       // 0
    proj_all<<<904, 256>>>(image, text, Wq, Wk, Wv);                     // 1
    kprep_kernel<<<T_*H_, 256>>>();                                      // 2
    dummy_kernel<<<1, 32>>>();                                           // 3
    dummy_kernel<<<1, 32>>>();                                           // 4

    int wAttn = out_size >= (OUT_N + ATT_N);
    int wText = out_size >= (OUT_N + 2*ATT_N);
    attn_kernel<<<I_*H_, 256, SMEM_ATTN>>>(out, wAttn, wText);           // 5

    if (out_size >= OUT_N)
        fc_kernel<<<dim3(16, 8), 256>>>(Wo, bo, out);                    // 6
}

// round 8
// speedup vs baseline: 1.0023x; 1.0023x over previous
#include <cuda_runtime.h>
#include <cuda_bf16.h>
#include <math.h>
#include <cstdint>

#define I_ 16
#define T_ 64
#define Q_ 196
#define K_ 32
#define E_ 512
#define H_ 8
#define D_ 64

#define OUT_N   (I_*T_*E_)                  // 524288
#define ATT_N   (I_*T_*H_*Q_*K_)            // 51380224
#define SCALE_  0.044194173824159216f       // 1/sqrt(512)
#define LOG2E_  1.4426950408889634f
#define SC2_    (SCALE_*LOG2E_)

#define SA_  200                            // A/B smem stride (bf16 elems), padded
#define MR_  208                            // A rows (196 padded to 13*16)
#define EST_ 36                             // sE row stride (floats)

#define ABYTES   (MR_*SA_*2)                // 83200 (also holds sE: 208*36*4=29952)
#define BBUF     (K_*SA_*2)                 // 12800
#define B_OFF    ABYTES                     // 83200
#define V_OFF    (B_OFF + 2*BBUF)           // 108800
#define RINV_OFF (V_OFF + 2*K_*D_*4)        // 125184
#define MK_OFF   (RINV_OFF + MR_*4)         // 126016
#define CA_OFF   (MK_OFF + 256)             // 126272
#define TA_OFF   (CA_OFF + 128)             // 126400
#define TB_OFF   (TA_OFF + 128)             // 126528
#define SMEM_ATTN (TB_OFF + 128)            // 126656

// -------- scratch (device globals: no allocations allowed) --------
__device__ float g_query[I_*H_*Q_*D_];   // (i,h,q,d)
__device__ float g_key  [T_*H_*K_*D_];   // (t,h,k,d)
__device__ float g_value[T_*H_*K_*D_];   // (t,h,k,d)
__device__ float g_pooled[I_*T_*E_];     // (i*T+t, e)
__device__ float g_maskf[T_*K_];
__device__ unsigned char g_kb[(size_t)T_*H_*BBUF];   // pre-split bf16 B tiles [hi|lo|hi]

// -------- PTX helpers (sm_80-class, safe on plain sm_103 target) --------
__device__ __forceinline__ unsigned smem_u32(const void* p) {
    unsigned a;
    asm("{ .reg .u64 t; cvta.to.shared.u64 t, %1; cvt.u32.u64 %0, t; }" : "=r"(a) : "l"(p));
    return a;
}
__device__ __forceinline__ float ex2(float x) {          // single MUFU, no libm expansion
    float y;
    asm("ex2.approx.f32 %0, %1;" : "=f"(y) : "f"(x));
    return y;
}
__device__ __forceinline__ void ldm_x4(unsigned addr, unsigned& r0, unsigned& r1,
                                       unsigned& r2, unsigned& r3) {
    asm volatile("ldmatrix.sync.aligned.m8n8.x4.shared.b16 {%0,%1,%2,%3}, [%4];"
                 : "=r"(r0), "=r"(r1), "=r"(r2), "=r"(r3) : "r"(addr));
}
__device__ __forceinline__ void ldm_x2(unsigned addr, unsigned& r0, unsigned& r1) {
    asm volatile("ldmatrix.sync.aligned.m8n8.x2.shared.b16 {%0,%1}, [%2];"
                 : "=r"(r0), "=r"(r1) : "r"(addr));
}
__device__ __forceinline__ void mma_bf16(float* c, unsigned a0, unsigned a1, unsigned a2,
                                         unsigned a3, unsigned b0, unsigned b1) {
    asm volatile("mma.sync.aligned.m16n8k16.row.col.f32.bf16.bf16.f32 "
                 "{%0,%1,%2,%3}, {%4,%5,%6,%7}, {%8,%9}, {%0,%1,%2,%3};"
                 : "+f"(c[0]), "+f"(c[1]), "+f"(c[2]), "+f"(c[3])
                 : "r"(a0), "r"(a1), "r"(a2), "r"(a3), "r"(b0), "r"(b1));
}

// -------- dummy (ncu launch-slot alignment: attn lands on skip-5 capture) --------
__global__ void dummy_kernel() {}

// -------- mask conversion (robust to bool/int32/float32 serialization) --------
__global__ void mask_kernel(const void* mp) {
    __shared__ int mode;
    if (threadIdx.x == 0) {
        const unsigned char* b = (const unsigned char*)mp;
        int c3f = 0, cnz = 0;
        for (int k = 0; k < 512; k++) {
            if (b[4*k+3] == 0x3F) c3f++;
            if (b[4*k+1] | b[4*k+2]) cnz++;
        }
        mode = (c3f > 8) ? 2 : ((cnz > 8) ? 0 : 1);
    }
    __syncthreads();
    int m = mode;
    for (int idx = threadIdx.x; idx < T_*K_; idx += blockDim.x) {
        float v;
        if (m == 0)      v = ((const unsigned char*)mp)[idx] ? 1.f : 0.f;
        else if (m == 1) v = ((const int*)mp)[idx] ? 1.f : 0.f;
        else             v = (((const float*)mp)[idx] != 0.f) ? 1.f : 0.f;
        g_maskf[idx] = v;
    }
}

// -------- fused Q/K/V projections, one launch (904 CTAs) --------
__global__ void proj_all(const float* __restrict__ image, const float* __restrict__ text,
                         const float* __restrict__ Wq, const float* __restrict__ Wk,
                         const float* __restrict__ Wv) {
    __shared__ float sA[64*33];
    __shared__ float sB[64*33];
    int bid = blockIdx.x;
    int which, h, rb;
    const float *X, *W;
    float* Y;
    if (bid < 392)      { which = 0; h = bid/49;        rb = bid%49;        X = image; W = Wq; Y = g_query; }
    else if (bid < 648) { which = 1; h = (bid-392)/32;  rb = (bid-392)%32;  X = text;  W = Wk; Y = g_key;   }
    else                { which = 2; h = (bid-648)/32;  rb = (bid-648)%32;  X = text;  W = Wv; Y = g_value; }
    int r0 = rb * 64;
    int tid = threadIdx.x;
    int tx = tid & 15, ty = tid >> 4;
    float acc[4][4] = {};

    #pragma unroll
    for (int kc = 0; kc < 64; kc += 32) {
        for (int idx = tid; idx < 2048; idx += 256) {
            int r = idx >> 5, kk = idx & 31;
            sA[r*33 + kk] = X[(r0 + r)*E_ + h*64 + kc + kk];
            sB[r*33 + kk] = W[r*64 + kc + kk];
        }
        __syncthreads();
        #pragma unroll
        for (int kk = 0; kk < 32; kk++) {
            float a[4], b[4];
            #pragma unroll
            for (int r = 0; r < 4; r++) a[r] = sA[(ty*4 + r)*33 + kk];
            #pragma unroll
            for (int c = 0; c < 4; c++) b[c] = sB[(tx*4 + c)*33 + kk];
            #pragma unroll
            for (int r = 0; r < 4; r++)
                #pragma unroll
                for (int c = 0; c < 4; c++) acc[r][c] += a[r] * b[c];
        }
        __syncthreads();
    }
    #pragma unroll
    for (int r = 0; r < 4; r++) {
        int row = r0 + ty*4 + r;
        long long obase;
        if (which == 0) { int i = row / Q_, q = row % Q_;  obase = ((long long)(i*H_ + h)*Q_ + q)*64; }
        else            { int t = row >> 5, k = row & 31;  obase = ((long long)(t*H_ + h)*K_ + k)*64; }
        #pragma unroll
        for (int c = 0; c < 4; c++)
            Y[obase + tx*4 + c] = acc[r][c];
    }
}

// -------- one-shot K split-conversion: g_key -> g_kb bf16 [hi|lo|hi], stride SA_ --------
__global__ void kprep_kernel() {
    int th = blockIdx.x, tid = threadIdx.x;
    const float* Kg = g_key + (size_t)th*(K_*D_);
    unsigned char* B = g_kb + (size_t)th*BBUF;
    for (int idx = tid; idx < (K_*D_)/2; idx += 256) {
        int k = idx >> 5, d2 = (idx & 31)*2;
        float2 x = *(const float2*)&Kg[k*64 + d2];
        __nv_bfloat162 hi = __floats2bfloat162_rn(x.x, x.y);
        float2 hf = __bfloat1622float2(hi);
        __nv_bfloat162 lo = __floats2bfloat162_rn(x.x - hf.x, x.y - hf.y);
        *(__nv_bfloat162*)(B + (k*SA_ + d2)*2)       = hi;
        *(__nv_bfloat162*)(B + (k*SA_ + 64 + d2)*2)  = lo;
        *(__nv_bfloat162*)(B + (k*SA_ + 128 + d2)*2) = hi;
    }
}

// -------- fused warp-MMA energy + dual softmax + pooled-AV --------
// grid 128 (= i*8 + h), 256 threads, occ 1. Split bf16: A=[hi|hi|lo], B=[hi|lo|hi], K=192.
__global__ void __launch_bounds__(256, 1)
attn_kernel(float* __restrict__ out, int wAttn, int wText) {
    extern __shared__ unsigned char smem[];
    unsigned sbase = smem_u32(smem);
    float* sE    = (float*)smem;                    // overlaps A region (A consumed into regs)
    float* sV    = (float*)(smem + V_OFF);
    float* sRinv = (float*)(smem + RINV_OFF);
    float* sMkA  = (float*)(smem + MK_OFF);
    float* sCA   = (float*)(smem + CA_OFF);
    float* sTA   = (float*)(smem + TA_OFF);
    float* sTB   = (float*)(smem + TB_OFF);

    int ih = blockIdx.x;
    int h = ih & 7, i = ih >> 3;
    int tid = threadIdx.x, lane = tid & 31, wid = tid >> 5;

    // ---- stage A (Q tile) as bf16 split into padded smem ----
    {
        unsigned* z = (unsigned*)smem;
        for (int idx = tid; idx < (MR_*SA_)/2; idx += 256) z[idx] = 0u;
        __syncthreads();
        const float* Qg = g_query + (size_t)ih*(Q_*D_);
        unsigned char* A = smem;
        for (int idx = tid; idx < (Q_*D_)/2; idx += 256) {
            int q = idx >> 5, d2 = (idx & 31)*2;
            float2 x = *(const float2*)&Qg[q*64 + d2];
            __nv_bfloat162 hi = __floats2bfloat162_rn(x.x, x.y);
            float2 hf = __bfloat1622float2(hi);
            __nv_bfloat162 lo = __floats2bfloat162_rn(x.x - hf.x, x.y - hf.y);
            *(__nv_bfloat162*)(A + (q*SA_ + d2)*2)       = hi;
            *(__nv_bfloat162*)(A + (q*SA_ + 64 + d2)*2)  = hi;
            *(__nv_bfloat162*)(A + (q*SA_ + 128 + d2)*2) = lo;
        }
        __syncthreads();
    }

    // ---- hoist A fragments into registers (reused for all 64 t-tiles) ----
    unsigned af[2][12][4];
    bool has2 = (wid + 8) < 13;
    {
        int lrow = lane & 15;
        int lcol = (lane < 16) ? 0 : 8;
        #pragma unroll
        for (int wti = 0; wti < 2; wti++) {
            int wt = wid + wti*8;
            if (wti == 0 || has2) {
                #pragma unroll
                for (int ks = 0; ks < 12; ks++) {
                    unsigned addr = sbase + (unsigned)(((wt*16 + lrow)*SA_ + ks*16 + lcol)*2);
                    ldm_x4(addr, af[wti][ks][0], af[wti][ks][1], af[wti][ks][2], af[wti][ks][3]);
                }
            }
        }
    }

    // ---- stage t=0 K/V/mask into buffer 0 (pure copies; K pre-split in g_kb) ----
    {
        const float4* bs = (const float4*)(g_kb + (size_t)(0*H_ + h)*BBUF);
        float4* bd = (float4*)(smem + B_OFF);
        for (int idx = tid; idx < BBUF/16; idx += 256) bd[idx] = bs[idx];
        const float4* vs = (const float4*)(g_value + (size_t)(0*H_ + h)*(K_*D_));
        float4* vd = (float4*)sV;
        for (int idx = tid; idx < (K_*D_)/4; idx += 256) vd[idx] = vs[idx];
        if (tid < K_) sMkA[tid] = g_maskf[0*K_ + tid];
    }
    __syncthreads();

    int p = 0;
    for (int t = 0; t < T_; t++) {
        // ---- MMA phase: energy for tile t into sE (row-major, stride 36) ----
        {
            unsigned sBb = sbase + B_OFF + (unsigned)(p*BBUF);
            int ln = lane & 15;
            int bn = ln & 7;
            int bc = (ln < 8) ? 0 : 8;
            float c[2][4][4];
            #pragma unroll
            for (int a = 0; a < 2; a++)
                #pragma unroll
                for (int nt = 0; nt < 4; nt++)
                    #pragma unroll
                    for (int r = 0; r < 4; r++) c[a][nt][r] = 0.f;
            #pragma unroll
            for (int ks = 0; ks < 12; ks++) {
                unsigned b0[4], b1[4];
                #pragma unroll
                for (int nt = 0; nt < 4; nt++) {
                    unsigned addr = sBb + (unsigned)(((nt*8 + bn)*SA_ + ks*16 + bc)*2);
                    ldm_x2(addr, b0[nt], b1[nt]);
                }
                #pragma unroll
                for (int nt = 0; nt < 4; nt++) {
                    mma_bf16(c[0][nt], af[0][ks][0], af[0][ks][1], af[0][ks][2], af[0][ks][3],
                             b0[nt], b1[nt]);
                    if (has2)
                        mma_bf16(c[1][nt], af[1][ks][0], af[1][ks][1], af[1][ks][2], af[1][ks][3],
                                 b0[nt], b1[nt]);
                }
            }
            int g = lane >> 2, q2 = lane & 3;
            #pragma unroll
            for (int wti = 0; wti < 2; wti++) {
                if (wti == 1 && !has2) break;
                int r0 = (wid + wti*8)*16 + g;
                #pragma unroll
                for (int nt = 0; nt < 4; nt++) {
                    int col = nt*8 + 2*q2;
                    *(float2*)&sE[r0*EST_ + col]       = make_float2(c[wti][nt][0], c[wti][nt][1]);
                    *(float2*)&sE[(r0 + 8)*EST_ + col] = make_float2(c[wti][nt][2], c[wti][nt][3]);
                }
            }
        }

        // ---- prefetch tile t+1 into other buffers (overlaps tensor execution) ----
        if (t + 1 < T_) {
            int pn = p ^ 1;
            const float4* bs = (const float4*)(g_kb + (size_t)((t+1)*H_ + h)*BBUF);
            float4* bd = (float4*)(smem + B_OFF + pn*BBUF);
            for (int idx = tid; idx < BBUF/16; idx += 256) bd[idx] = bs[idx];
            const float4* vs = (const float4*)(g_value + (size_t)((t+1)*H_ + h)*(K_*D_));
            float4* vd = (float4*)(sV + pn*(K_*D_));
            for (int idx = tid; idx < (K_*D_)/4; idx += 256) vd[idx] = vs[idx];
            if (tid < K_) sMkA[pn*32 + tid] = g_maskf[(t+1)*K_ + tid];
        }
        __syncthreads();

        const float* mk = sMkA + p*32;

        // ---- exp + row sums (thread owns q-row; conflict-free float4; raw MUFU) ----
        if (tid < Q_) {
            float4* row = (float4*)(sE + tid*EST_);
            float rowsum = 0.f;
            #pragma unroll
            for (int j = 0; j < 8; j++) {
                float4 v = row[j];
                v.x = (mk[4*j + 0] != 0.f) ? ex2(v.x * SC2_) : 0.f;
                v.y = (mk[4*j + 1] != 0.f) ? ex2(v.y * SC2_) : 0.f;
                v.z = (mk[4*j + 2] != 0.f) ? ex2(v.z * SC2_) : 0.f;
                v.w = (mk[4*j + 3] != 0.f) ? ex2(v.w * SC2_) : 0.f;
                rowsum += (v.x + v.y) + (v.z + v.w);
                row[j] = v;
            }
            sRinv[tid] = 1.f / rowsum;
        }
        __syncthreads();

        // ---- column sums (8 threads per k, conflict-free) ----
        {
            int kcol = tid >> 3, qoff = tid & 7;
            float pe = 0.f, pa = 0.f;
            for (int q = qoff; q < Q_; q += 8) {
                float ee = sE[q*EST_ + kcol];
                pe += ee; pa += ee * sRinv[q];
            }
            #pragma unroll
            for (int o = 4; o > 0; o >>= 1) {
                pe += __shfl_xor_sync(0xffffffffu, pe, o);
                pa += __shfl_xor_sync(0xffffffffu, pa, o);
            }
            if (qoff == 0) {
                float m = mk[kcol];
                sCA[kcol] = pa;
                sTA[kcol] = (m != 0.f) ? (1.f / pe) : 0.f;
                sTB[kcol] = (m != 0.f) ? 0.f : (1.f / (float)Q_);
            }
        }
        __syncthreads();

        // ---- writeout (STG.128 only) + pooled ----
        long long tileOff = ((long long)(i*T_ + t)*H_ + h) * (Q_*K_);
        if (wAttn | wText) {
            float4* attn4 = (float4*)(out + OUT_N + tileOff);
            float4* text4 = (float4*)(out + OUT_N + (long long)ATT_N + tileOff);
            const float4* sE4 = (const float4*)sE;
            const float4* tA4 = (const float4*)sTA;
            const float4* tB4 = (const float4*)sTB;
            for (int idx = tid; idx < Q_*8; idx += 256) {
                int q = idx >> 3, c = idx & 7;
                float4 e4 = sE4[q*(EST_/4) + c];
                if (wAttn) {
                    float r = sRinv[q];
                    float4 a4 = { e4.x*r, e4.y*r, e4.z*r, e4.w*r };
                    attn4[idx] = a4;
                }
                if (wText) {
                    float4 ta = tA4[c], tb = tB4[c];
                    float4 x4 = { fmaf(e4.x, ta.x, tb.x), fmaf(e4.y, ta.y, tb.y),
                                  fmaf(e4.z, ta.z, tb.z), fmaf(e4.w, ta.w, tb.w) };
                    text4[idx] = x4;
                }
            }
        }
        if (tid < 64) {
            float a = 0.f;
            const float* vv = sV + p*(K_*D_);
            #pragma unroll
            for (int k = 0; k < 32; k++) a += sCA[k] * vv[k*D_ + tid];
            g_pooled[(long long)(i*T_ + t)*E_ + h*64 + tid] = a * (1.f / (float)Q_);
        }
        __syncthreads();
        p ^= 1;
    }
}

// -------- final: out[row,f] = sum_e pooled[row,e]*Wo[f,e] + bo[f] (reg-prefetched) --------
__global__ void fc_kernel(const float* __restrict__ Wo, const float* __restrict__ bo,
                          float* __restrict__ out) {
    __shared__ float sA[64*33];
    __shared__ float sB[64*33];
    int rt = blockIdx.x * 64;
    int ct = blockIdx.y * 64;
    int tid = threadIdx.x;
    int tx = tid & 15, ty = tid >> 4;
    float acc[4][4] = {};
    float ra[8], rb[8];

    #pragma unroll
    for (int j = 0; j < 8; j++) {
        int idx = tid + j*256;
        int r = idx >> 5, kk = idx & 31;
        ra[j] = g_pooled[(rt + r)*E_ + kk];
        rb[j] = Wo[(ct + r)*E_ + kk];
    }
    for (int kc = 0; kc < E_; kc += 32) {
        #pragma unroll
        for (int j = 0; j < 8; j++) {
            int idx = tid + j*256;
            int r = idx >> 5, kk = idx & 31;
            sA[r*33 + kk] = ra[j];
            sB[r*33 + kk] = rb[j];
        }
        __syncthreads();
        if (kc + 32 < E_) {
            #pragma unroll
            for (int j = 0; j < 8; j++) {
                int idx = tid + j*256;
                int r = idx >> 5, kk = idx & 31;
                ra[j] = g_pooled[(rt + r)*E_ + kc + 32 + kk];
                rb[j] = Wo[(ct + r)*E_ + kc + 32 + kk];
            }
        }
        #pragma unroll
        for (int kk = 0; kk < 32; kk++) {
            float a[4], b[4];
            #pragma unroll
            for (int r = 0; r < 4; r++) a[r] = sA[(ty*4 + r)*33 + kk];
            #pragma unroll
            for (int c = 0; c < 4; c++) b[c] = sB[(tx*4 + c)*33 + kk];
            #pragma unroll
            for (int r = 0; r < 4; r++)
                #pragma unroll
                for (int c = 0; c < 4; c++) acc[r][c] += a[r] * b[c];
        }
        __syncthreads();
    }
    #pragma unroll
    for (int r = 0; r < 4; r++)
        #pragma unroll
        for (int c = 0; c < 4; c++)
            out[(rt + ty*4 + r)*E_ + ct + tx*4 + c] = acc[r][c] + bo[ct + tx*4 + c];
}

// -------- launch --------
extern "C" void kernel_launch(void* const* d_in, const int* in_sizes, int n_in,
                              void* d_out, int out_size) {
    const float* image = (const float*)d_in[0];
    const float* text  = (const float*)d_in[1];
    const void*  mask  =                d_in[2];
    const float* Wq    = (const float*)d_in[3];
    const float* Wk    = (const float*)d_in[4];
    const float* Wv    = (const float*)d_in[5];
    const float* Wo    = (const float*)d_in[6];
    const float* bo    = (const float*)d_in[7];
    float* out = (float*)d_out;

    cudaFuncSetAttribute(attn_kernel, cudaFuncAttributeMaxDynamicSharedMemorySize, SMEM_ATTN);

    // 7 launches/call -> ncu's skip-5 capture slot (5 mod 7) is always attn_kernel
    mask_kernel<<<1, 256>>>(mask);                                       // 0
    proj_all<<<904, 256>>>(image, text, Wq, Wk, Wv);                     // 1
    kprep_kernel<<<T_*H_, 256>>>();                                      // 2
    dummy_kernel<<<1, 32>>>();                                           // 3
    dummy_kernel<<<1, 32>>>();                                           // 4

    int wAttn = out_size >= (OUT_N + ATT_N);
    int wText = out_size >= (OUT_N + 2*ATT_N);
    attn_kernel<<<I_*H_, 256, SMEM_ATTN>>>(out, wAttn, wText);           // 5

    if (out_size >= OUT_N)
        fc_kernel<<<dim3(16, 8), 256>>>(Wo, bo, out);                    // 6
}

// round 9
// speedup vs baseline: 1.2932x; 1.2903x over previous
#include <cuda_runtime.h>
#include <cuda_bf16.h>
#include <math.h>
#include <cstdint>

#define I_ 16
#define T_ 64
#define Q_ 196
#define K_ 32
#define E_ 512
#define H_ 8
#define D_ 64
#define NT_ 512

#define OUT_N   (I_*T_*E_)
#define ATT_N   (I_*T_*H_*Q_*K_)
#define SC2_    ((float)(0.044194173824159216*1.4426950408889634))

#define SA_  200
#define MR_  208
#define EST_ 36
#define BBUF (K_*SA_*2)                 // 12800

#define B_OFF    83200                  // A/sE region is [0, 83200)
#define V_OFF    (B_OFF + 2*BBUF)       // 108800
#define RINV_OFF (V_OFF + 2*8192)       // 125184
#define MK_OFF   126016
#define YO_OFF   126272
#define CA_OFF   126528
#define TA_OFF   126656
#define TB_OFF   126784
#define PE_OFF   126912
#define PA_OFF   128960
#define SMEM_ATTN 131008

typedef unsigned long long ull;

__device__ float g_query[I_*H_*Q_*D_];
__device__ float g_key  [T_*H_*K_*D_];
__device__ float g_value[T_*H_*K_*D_];
__device__ float g_pooled[I_*T_*E_];
__device__ float g_maskf[T_*K_];
__device__ unsigned char g_kb[(size_t)T_*H_*BBUF];

__device__ __forceinline__ unsigned smem_u32(const void* p) {
    unsigned a;
    asm("{ .reg .u64 t; cvta.to.shared.u64 t, %1; cvt.u32.u64 %0, t; }" : "=r"(a) : "l"(p));
    return a;
}
__device__ __forceinline__ ull fma2(ull a, ull b, ull c) {
    ull d; asm("fma.rn.f32x2 %0, %1, %2, %3;" : "=l"(d) : "l"(a), "l"(b), "l"(c)); return d;
}
__device__ __forceinline__ ull mul2(ull a, ull b) {
    ull d; asm("mul.rn.f32x2 %0, %1, %2;" : "=l"(d) : "l"(a), "l"(b)); return d;
}
__device__ __forceinline__ ull add2(ull a, ull b) {
    ull d; asm("add.rn.f32x2 %0, %1, %2;" : "=l"(d) : "l"(a), "l"(b)); return d;
}
__device__ __forceinline__ ull pack2(float x, float y) {
    ull d; asm("mov.b64 %0, {%1, %2};" : "=l"(d) : "f"(x), "f"(y)); return d;
}
__device__ __forceinline__ float lo2(ull a) { return __uint_as_float((unsigned)a); }
__device__ __forceinline__ float hi2(ull a) { return __uint_as_float((unsigned)(a >> 32)); }
__device__ __forceinline__ float ex2(float x) {
    float y; asm("ex2.approx.f32 %0, %1;" : "=f"(y) : "f"(x)); return y;
}
__device__ __forceinline__ float rcpa(float x) {
    float y; asm("rcp.approx.f32 %0, %1;" : "=f"(y) : "f"(x)); return y;
}
__device__ __forceinline__ void lds2(unsigned a, ull& x, ull& y) {
    asm volatile("ld.shared.v2.b64 {%0,%1}, [%2];" : "=l"(x), "=l"(y) : "r"(a));
}
__device__ __forceinline__ void sts2(unsigned a, ull x, ull y) {
    asm volatile("st.shared.v2.b64 [%0], {%1,%2};" :: "r"(a), "l"(x), "l"(y) : "memory");
}
__device__ __forceinline__ void stg4(float* p, ull a, ull b) {
    asm volatile("{ .reg .f32 x,y,z,w; mov.b64 {x,y}, %1; mov.b64 {z,w}, %2;"
                 " st.global.v4.f32 [%0], {x,y,z,w}; }" :: "l"(p), "l"(a), "l"(b) : "memory");
}
__device__ __forceinline__ void ldm_x4(unsigned a, unsigned& r0, unsigned& r1,
                                       unsigned& r2, unsigned& r3) {
    asm volatile("ldmatrix.sync.aligned.m8n8.x4.shared.b16 {%0,%1,%2,%3}, [%4];"
                 : "=r"(r0), "=r"(r1), "=r"(r2), "=r"(r3) : "r"(a));
}
__device__ __forceinline__ void ldm_x2(unsigned a, unsigned& r0, unsigned& r1) {
    asm volatile("ldmatrix.sync.aligned.m8n8.x2.shared.b16 {%0,%1}, [%2];"
                 : "=r"(r0), "=r"(r1) : "r"(a));
}
__device__ __forceinline__ void mma_bf16(float* c, unsigned a0, unsigned a1, unsigned a2,
                                         unsigned a3, unsigned b0, unsigned b1) {
    asm volatile("mma.sync.aligned.m16n8k16.row.col.f32.bf16.bf16.f32 "
                 "{%0,%1,%2,%3}, {%4,%5,%6,%7}, {%8,%9}, {%0,%1,%2,%3};"
                 : "+f"(c[0]), "+f"(c[1]), "+f"(c[2]), "+f"(c[3])
                 : "r"(a0), "r"(a1), "r"(a2), "r"(a3), "r"(b0), "r"(b1));
}

__global__ void mask_kernel(const void* mp) {
    __shared__ int mode;
    if (threadIdx.x == 0) {
        const unsigned char* b = (const unsigned char*)mp;
        int c3f = 0, cnz = 0;
        for (int k = 0; k < 512; k++) {
            if (b[4*k+3] == 0x3F) c3f++;
            if (b[4*k+1] | b[4*k+2]) cnz++;
        }
        mode = (c3f > 8) ? 2 : ((cnz > 8) ? 0 : 1);
    }
    __syncthreads();
    int m = mode;
    for (int idx = threadIdx.x; idx < T_*K_; idx += blockDim.x) {
        float v;
        if (m == 0)      v = ((const unsigned char*)mp)[idx] ? 1.f : 0.f;
        else if (m == 1) v = ((const int*)mp)[idx] ? 1.f : 0.f;
        else             v = (((const float*)mp)[idx] != 0.f) ? 1.f : 0.f;
        g_maskf[idx] = v;
    }
}

__global__ void proj_all(const float* __restrict__ image, const float* __restrict__ text,
                         const float* __restrict__ Wq, const float* __restrict__ Wk,
                         const float* __restrict__ Wv) {
    __shared__ float sA[64*33];
    __shared__ float sB[64*33];
    int bid = blockIdx.x;
    int which, h, rb;
    const float *X, *W;
    float* Y;
    if (bid < 392)      { which = 0; h = bid/49;       rb = bid%49;       X = image; W = Wq; Y = g_query; }
    else if (bid < 648) { which = 1; h = (bid-392)/32; rb = (bid-392)%32; X = text;  W = Wk; Y = g_key;   }
    else                { which = 2; h = (bid-648)/32; rb = (bid-648)%32; X = text;  W = Wv; Y = g_value; }
    int r0 = rb * 64;
    int tid = threadIdx.x;
    int tx = tid & 15, ty = tid >> 4;
    float acc[4][4] = {};
    #pragma unroll
    for (int kc = 0; kc < 64; kc += 32) {
        for (int idx = tid; idx < 2048; idx += 256) {
            int r = idx >> 5, kk = idx & 31;
            sA[r*33 + kk] = X[(r0 + r)*E_ + h*64 + kc + kk];
            sB[r*33 + kk] = W[r*64 + kc + kk];
        }
        __syncthreads();
        #pragma unroll
        for (int kk = 0; kk < 32; kk++) {
            float a[4], b[4];
            #pragma unroll
            for (int r = 0; r < 4; r++) a[r] = sA[(ty*4 + r)*33 + kk];
            #pragma unroll
            for (int c = 0; c < 4; c++) b[c] = sB[(tx*4 + c)*33 + kk];
            #pragma unroll
            for (int r = 0; r < 4; r++)
                #pragma unroll
                for (int c = 0; c < 4; c++) acc[r][c] += a[r] * b[c];
        }
        __syncthreads();
    }
    #pragma unroll
    for (int r = 0; r < 4; r++) {
        int row = r0 + ty*4 + r;
        long long obase;
        if (which == 0) { int i = row / Q_, q = row % Q_; obase = ((long long)(i*H_ + h)*Q_ + q)*64; }
        else            { int t = row >> 5, k = row & 31; obase = ((long long)(t*H_ + h)*K_ + k)*64; }
        #pragma unroll
        for (int c = 0; c < 4; c++)
            Y[obase + tx*4 + c] = acc[r][c];
    }
}

__global__ void kprep_kernel() {
    int th = blockIdx.x, tid = threadIdx.x;
    const float* Kg = g_key + (size_t)th*(K_*D_);
    unsigned char* B = g_kb + (size_t)th*BBUF;
    for (int idx = tid; idx < (K_*D_)/2; idx += 256) {
        int k = idx >> 5, d2 = (idx & 31)*2;
        float2 x = *(const float2*)&Kg[k*64 + d2];
        __nv_bfloat162 hi = __floats2bfloat162_rn(x.x, x.y);
        float2 hf = __bfloat1622float2(hi);
        __nv_bfloat162 lo = __floats2bfloat162_rn(x.x - hf.x, x.y - hf.y);
        *(__nv_bfloat162*)(B + (k*SA_ + d2)*2)       = hi;
        *(__nv_bfloat162*)(B + (k*SA_ + 64 + d2)*2)  = lo;
        *(__nv_bfloat162*)(B + (k*SA_ + 128 + d2)*2) = hi;
    }
}

__global__ void __launch_bounds__(NT_, 1)
attn_kernel(float* __restrict__ out, int wAttn, int wText) {
    extern __shared__ unsigned char smem[];
    unsigned sbase = smem_u32(smem);
    float* sE    = (float*)smem;
    float* sV    = (float*)(smem + V_OFF);
    float* sRinv = (float*)(smem + RINV_OFF);
    float* sMkA  = (float*)(smem + MK_OFF);
    float* sYO   = (float*)(smem + YO_OFF);
    float* sCA   = (float*)(smem + CA_OFF);
    float* sTA   = (float*)(smem + TA_OFF);
    float* sTB   = (float*)(smem + TB_OFF);
    float* sPE   = (float*)(smem + PE_OFF);
    float* sPA   = (float*)(smem + PA_OFF);

    int ih = blockIdx.x;
    int h = ih & 7, i = ih >> 3;
    int tid = threadIdx.x, lane = tid & 31, wid = tid >> 5;

    // ---- stage A (bf16 split, zero-padded to 208 rows) ----
    {
        unsigned* z = (unsigned*)smem;
        for (int idx = tid; idx < (MR_*SA_)/2; idx += NT_) z[idx] = 0u;
        __syncthreads();
        const float* Qg = g_query + (size_t)ih*(Q_*D_);
        unsigned char* A = smem;
        for (int idx = tid; idx < (Q_*D_)/2; idx += NT_) {
            int q = idx >> 5, d2 = (idx & 31)*2;
            float2 x = *(const float2*)&Qg[q*64 + d2];
            __nv_bfloat162 hi = __floats2bfloat162_rn(x.x, x.y);
            float2 hf = __bfloat1622float2(hi);
            __nv_bfloat162 lo = __floats2bfloat162_rn(x.x - hf.x, x.y - hf.y);
            *(__nv_bfloat162*)(A + (q*SA_ + d2)*2)       = hi;
            *(__nv_bfloat162*)(A + (q*SA_ + 64 + d2)*2)  = hi;
            *(__nv_bfloat162*)(A + (q*SA_ + 128 + d2)*2) = lo;
        }
        __syncthreads();
    }

    // ---- hoist A fragments: warp w (<13) owns rows w*16..+15 ----
    unsigned af[12][4];
    if (wid < 13) {
        int lrow = lane & 15;
        int lcol = (lane < 16) ? 0 : 8;
        #pragma unroll
        for (int ks = 0; ks < 12; ks++) {
            unsigned a = sbase + (unsigned)(((wid*16 + lrow)*SA_ + ks*16 + lcol)*2);
            ldm_x4(a, af[ks][0], af[ks][1], af[ks][2], af[ks][3]);
        }
    }

    // ---- stage t=0 B/V/mask/yoff ----
    {
        const float4* bs = (const float4*)(g_kb + (size_t)(0*H_ + h)*BBUF);
        float4* bd = (float4*)(smem + B_OFF);
        for (int idx = tid; idx < BBUF/16; idx += NT_) bd[idx] = bs[idx];
        const float4* vs = (const float4*)(g_value + (size_t)(0*H_ + h)*(K_*D_));
        float4* vd = (float4*)sV;
        for (int idx = tid; idx < (K_*D_)/4; idx += NT_) vd[idx] = vs[idx];
        if (tid < K_) {
            float m = g_maskf[0*K_ + tid];
            sMkA[tid] = m;
            sYO[tid] = (m != 0.f) ? 0.f : -1e30f;
        }
    }
    __syncthreads();

    int p = 0;
    const ull S2 = pack2(SC2_, SC2_);

    for (int t = 0; t < T_; t++) {
        long long tileOff = ((long long)(i*T_ + t)*H_ + h) * (Q_*K_);

        // ---- MMA: warp w -> rows w*16..+15, all 32 cols ----
        if (wid < 13) {
            unsigned sBb = sbase + B_OFF + (unsigned)(p*BBUF);
            int ln = lane & 15;
            int bn = ln & 7;
            int bc = (ln < 8) ? 0 : 8;
            float c[4][4] = {};
            #pragma unroll
            for (int ks = 0; ks < 12; ks++) {
                unsigned b0[4], b1[4];
                #pragma unroll
                for (int nt = 0; nt < 4; nt++) {
                    unsigned a = sBb + (unsigned)(((nt*8 + bn)*SA_ + ks*16 + bc)*2);
                    ldm_x2(a, b0[nt], b1[nt]);
                }
                #pragma unroll
                for (int nt = 0; nt < 4; nt++)
                    mma_bf16(c[nt], af[ks][0], af[ks][1], af[ks][2], af[ks][3], b0[nt], b1[nt]);
            }
            int g = lane >> 2, q2 = lane & 3;
            int r0 = wid*16 + g;
            #pragma unroll
            for (int nt = 0; nt < 4; nt++) {
                int col = nt*8 + 2*q2;
                *(float2*)&sE[r0*EST_ + col]       = make_float2(c[nt][0], c[nt][1]);
                *(float2*)&sE[(r0 + 8)*EST_ + col] = make_float2(c[nt][2], c[nt][3]);
            }
        }

        // ---- prefetch t+1 ----
        if (t + 1 < T_) {
            int pn = p ^ 1;
            const float4* bs = (const float4*)(g_kb + (size_t)((t+1)*H_ + h)*BBUF);
            float4* bd = (float4*)(smem + B_OFF + pn*BBUF);
            for (int idx = tid; idx < BBUF/16; idx += NT_) bd[idx] = bs[idx];
            const float4* vs = (const float4*)(g_value + (size_t)((t+1)*H_ + h)*(K_*D_));
            float4* vd = (float4*)(sV + pn*(K_*D_));
            for (int idx = tid; idx < (K_*D_)/4; idx += NT_) vd[idx] = vs[idx];
            if (tid < K_) {
                float m = g_maskf[(t+1)*K_ + tid];
                sMkA[pn*32 + tid] = m;
                sYO[pn*32 + tid] = (m != 0.f) ? 0.f : -1e30f;
            }
        }
        __syncthreads();

        // ---- exp + rowsum + direct attn store (thread-pair owns q-row) ----
        if (tid < 416) {
            int row = tid >> 1, half = tid & 1;
            unsigned ea = sbase + (unsigned)((row*EST_ + half*16)*4);
            unsigned ya = sbase + YO_OFF + (unsigned)(p*128 + half*64);
            ull ep[8];
            ull rs = pack2(0.f, 0.f);
            #pragma unroll
            for (int j = 0; j < 4; j++) {
                ull u0, u1, y0, y1;
                lds2(ea + j*16, u0, u1);
                lds2(ya + j*16, y0, y1);
                y0 = fma2(u0, S2, y0);
                y1 = fma2(u1, S2, y1);
                ull p0 = pack2(ex2(lo2(y0)), ex2(hi2(y0)));
                ull p1 = pack2(ex2(lo2(y1)), ex2(hi2(y1)));
                rs = add2(rs, p0);
                rs = add2(rs, p1);
                sts2(ea + j*16, p0, p1);
                ep[2*j] = p0; ep[2*j+1] = p1;
            }
            float rsum = lo2(rs) + hi2(rs);
            rsum += __shfl_xor_sync(0xffffffffu, rsum, 1);
            float rinv = rcpa(rsum);
            if (row < Q_) {
                if (half == 0) sRinv[row] = rinv;
                if (wAttn) {
                    float* ap = out + OUT_N + tileOff + row*K_ + half*16;
                    ull rv = pack2(rinv, rinv);
                    #pragma unroll
                    for (int j = 0; j < 4; j++)
                        stg4(ap + j*4, mul2(ep[2*j], rv), mul2(ep[2*j+1], rv));
                }
            }
        }
        __syncthreads();

        // ---- column partials: warp sweeps rows, lane = k (conflict-free) ----
        {
            float pe = 0.f, pa = 0.f;
            for (int q = wid; q < Q_; q += 16) {
                float e = sE[q*EST_ + lane];
                pe += e;
                pa = fmaf(e, sRinv[q], pa);
            }
            sPE[wid*32 + lane] = pe;
            sPA[wid*32 + lane] = pa;
        }
        __syncthreads();
        if (tid < 32) {
            float pe = 0.f, pa = 0.f;
            #pragma unroll
            for (int w = 0; w < 16; w++) { pe += sPE[w*32 + tid]; pa += sPA[w*32 + tid]; }
            float m = sMkA[p*32 + tid];
            sCA[tid] = pa;
            sTA[tid] = (m != 0.f) ? rcpa(pe) : 0.f;
            sTB[tid] = (m != 0.f) ? 0.f : (1.f / (float)Q_);
        }
        __syncthreads();

        // ---- text writeout + pooled ----
        if (wText) {
            float* tbase = out + OUT_N + (long long)ATT_N + tileOff;
            for (int idx = tid; idx < Q_*8; idx += NT_) {
                int q = idx >> 3, c = idx & 7;
                ull e0, e1, ta0, ta1, tb0, tb1;
                lds2(sbase + (unsigned)((q*EST_ + 4*c)*4), e0, e1);
                lds2(sbase + TA_OFF + (unsigned)(16*c), ta0, ta1);
                lds2(sbase + TB_OFF + (unsigned)(16*c), tb0, tb1);
                stg4(tbase + q*K_ + 4*c, fma2(e0, ta0, tb0), fma2(e1, ta1, tb1));
            }
        }
        if (tid < 64) {
            float a = 0.f;
            const float* vv = sV + p*(K_*D_);
            #pragma unroll
            for (int k = 0; k < 32; k++) a += sCA[k] * vv[k*D_ + tid];
            g_pooled[(long long)(i*T_ + t)*E_ + h*64 + tid] = a * (1.f / (float)Q_);
        }
        __syncthreads();
        p ^= 1;
    }
}

__global__ void fc_kernel(const float* __restrict__ Wo, const float* __restrict__ bo,
                          float* __restrict__ out) {
    __shared__ float sA[64*33];
    __shared__ float sB[64*33];
    int rt = blockIdx.x * 64;
    int ct = blockIdx.y * 64;
    int tid = threadIdx.x;
    int tx = tid & 15, ty = tid >> 4;
    float acc[4][4] = {};
    float ra[8], rb[8];
    #pragma unroll
    for (int j = 0; j < 8; j++) {
        int idx = tid + j*256;
        int r = idx >> 5, kk = idx & 31;
        ra[j] = g_pooled[(rt + r)*E_ + kk];
        rb[j] = Wo[(ct + r)*E_ + kk];
    }
    for (int kc = 0; kc < E_; kc += 32) {
        #pragma unroll
        for (int j = 0; j < 8; j++) {
            int idx = tid + j*256;
            int r = idx >> 5, kk = idx & 31;
            sA[r*33 + kk] = ra[j];
            sB[r*33 + kk] = rb[j];
        }
        __syncthreads();
        if (kc + 32 < E_) {
            #pragma unroll
            for (int j = 0; j < 8; j++) {
                int idx = tid + j*256;
                int r = idx >> 5, kk = idx & 31;
                ra[j] = g_pooled[(rt + r)*E_ + kc + 32 + kk];
                rb[j] = Wo[(ct + r)*E_ + kc + 32 + kk];
            }
        }
        #pragma unroll
        for (int kk = 0; kk < 32; kk++) {
            float a[4], b[4];
            #pragma unroll
            for (int r = 0; r < 4; r++) a[r] = sA[(ty*4 + r)*33 + kk];
            #pragma unroll
            for (int c = 0; c < 4; c++) b[c] = sB[(tx*4 + c)*33 + kk];
            #pragma unroll
            for (int r = 0; r < 4; r++)
                #pragma unroll
                for (int c = 0; c < 4; c++) acc[r][c] += a[r] * b[c];
        }
        __syncthreads();
    }
    #pragma unroll
    for (int r = 0; r < 4; r++)
        #pragma unroll
        for (int c = 0; c < 4; c++)
            out[(rt + ty*4 + r)*E_ + ct + tx*4 + c] = acc[r][c] + bo[ct + tx*4 + c];
}

extern "C" void kernel_launch(void* const* d_in, const int* in_sizes, int n_in,
                              void* d_out, int out_size) {
    const float* image = (const float*)d_in[0];
    const float* text  = (const float*)d_in[1];
    const void*  mask  =                d_in[2];
    const float* Wq    = (const float*)d_in[3];
    const float* Wk    = (const float*)d_in[4];
    const float* Wv    = (const float*)d_in[5];
    const float* Wo    = (const float*)d_in[6];
    const float* bo    = (const float*)d_in[7];
    float* out = (float*)d_out;

    cudaFuncSetAttribute(attn_kernel, cudaFuncAttributeMaxDynamicSharedMemorySize, SMEM_ATTN);

    mask_kernel<<<1, 256>>>(mask);
    proj_all<<<904, 256>>>(image, text, Wq, Wk, Wv);
    kprep_kernel<<<T_*H_, 256>>>();

    int wAttn = out_size >= (OUT_N + ATT_N);
    int wText = out_size >= (OUT_N + 2*ATT_N);
    attn_kernel<<<I_*H_, NT_, SMEM_ATTN>>>(out, wAttn, wText);

    if (out_size >= OUT_N)
        fc_kernel<<<dim3(16, 8), 256>>>(Wo, bo, out);
}

// round 10
// speedup vs baseline: 1.4157x; 1.0947x over previous
#include <cuda_runtime.h>
#include <cuda_bf16.h>
#include <math.h>
#include <cstdint>

#define I_ 16
#define T_ 64
#define Q_ 196
#define K_ 32
#define E_ 512
#define H_ 8
#define D_ 64
#define NT_ 512
#define NCTA_ 148
#define NU_ (I_*H_*T_)                  // 8192 units

#define OUT_N   (I_*T_*E_)
#define ATT_N   (I_*T_*H_*Q_*K_)
#define SC2_    ((float)(0.044194173824159216*1.4426950408889634))

#define SA_  200
#define MR_  208
#define EST_ 36
#define BBUF (K_*SA_*2)                 // 12800

#define B_OFF    83200
#define V_OFF    (B_OFF + 2*BBUF)       // 108800
#define RINV_OFF (V_OFF + 2*8192)       // 125184
#define MK_OFF   126016
#define YO_OFF   126272
#define CA_OFF   126528
#define TA_OFF   126656
#define TB_OFF   126784
#define PE_OFF   126912
#define PA_OFF   128960
#define SMEM_ATTN 131008

typedef unsigned long long ull;

__device__ float g_query[I_*H_*Q_*D_];
__device__ float g_key  [T_*H_*K_*D_];
__device__ float g_value[T_*H_*K_*D_];
__device__ float g_pooled[I_*T_*E_];
__device__ float g_maskf[T_*K_];
__device__ unsigned char g_kb[(size_t)T_*H_*BBUF];

__device__ __forceinline__ unsigned smem_u32(const void* p) {
    unsigned a;
    asm("{ .reg .u64 t; cvta.to.shared.u64 t, %1; cvt.u32.u64 %0, t; }" : "=r"(a) : "l"(p));
    return a;
}
__device__ __forceinline__ ull fma2(ull a, ull b, ull c) {
    ull d; asm("fma.rn.f32x2 %0, %1, %2, %3;" : "=l"(d) : "l"(a), "l"(b), "l"(c)); return d;
}
__device__ __forceinline__ ull mul2(ull a, ull b) {
    ull d; asm("mul.rn.f32x2 %0, %1, %2;" : "=l"(d) : "l"(a), "l"(b)); return d;
}
__device__ __forceinline__ ull add2(ull a, ull b) {
    ull d; asm("add.rn.f32x2 %0, %1, %2;" : "=l"(d) : "l"(a), "l"(b)); return d;
}
__device__ __forceinline__ ull pack2(float x, float y) {
    ull d; asm("mov.b64 %0, {%1, %2};" : "=l"(d) : "f"(x), "f"(y)); return d;
}
__device__ __forceinline__ float lo2(ull a) { return __uint_as_float((unsigned)a); }
__device__ __forceinline__ float hi2(ull a) { return __uint_as_float((unsigned)(a >> 32)); }
__device__ __forceinline__ float ex2(float x) {
    float y; asm("ex2.approx.f32 %0, %1;" : "=f"(y) : "f"(x)); return y;
}
__device__ __forceinline__ float rcpa(float x) {
    float y; asm("rcp.approx.f32 %0, %1;" : "=f"(y) : "f"(x)); return y;
}
__device__ __forceinline__ void lds2(unsigned a, ull& x, ull& y) {
    asm volatile("ld.shared.v2.b64 {%0,%1}, [%2];" : "=l"(x), "=l"(y) : "r"(a));
}
__device__ __forceinline__ ull lds1(unsigned a) {
    ull x; asm volatile("ld.shared.b64 %0, [%1];" : "=l"(x) : "r"(a)); return x;
}
__device__ __forceinline__ void stg4(float* p, ull a, ull b) {
    asm volatile("{ .reg .f32 x,y,z,w; mov.b64 {x,y}, %1; mov.b64 {z,w}, %2;"
                 " st.global.v4.f32 [%0], {x,y,z,w}; }" :: "l"(p), "l"(a), "l"(b) : "memory");
}
__device__ __forceinline__ void stg2(float* p, ull v) {
    asm volatile("{ .reg .f32 x,y; mov.b64 {x,y}, %1; st.global.v2.f32 [%0], {x,y}; }"
                 :: "l"(p), "l"(v) : "memory");
}
__device__ __forceinline__ void ldm_x4(unsigned a, unsigned& r0, unsigned& r1,
                                       unsigned& r2, unsigned& r3) {
    asm volatile("ldmatrix.sync.aligned.m8n8.x4.shared.b16 {%0,%1,%2,%3}, [%4];"
                 : "=r"(r0), "=r"(r1), "=r"(r2), "=r"(r3) : "r"(a));
}
__device__ __forceinline__ void ldm_x2(unsigned a, unsigned& r0, unsigned& r1) {
    asm volatile("ldmatrix.sync.aligned.m8n8.x2.shared.b16 {%0,%1}, [%2];"
                 : "=r"(r0), "=r"(r1) : "r"(a));
}
__device__ __forceinline__ void mma_bf16(float* c, unsigned a0, unsigned a1, unsigned a2,
                                         unsigned a3, unsigned b0, unsigned b1) {
    asm volatile("mma.sync.aligned.m16n8k16.row.col.f32.bf16.bf16.f32 "
                 "{%0,%1,%2,%3}, {%4,%5,%6,%7}, {%8,%9}, {%0,%1,%2,%3};"
                 : "+f"(c[0]), "+f"(c[1]), "+f"(c[2]), "+f"(c[3])
                 : "r"(a0), "r"(a1), "r"(a2), "r"(a3), "r"(b0), "r"(b1));
}

__global__ void mask_kernel(const void* mp) {
    __shared__ int mode;
    if (threadIdx.x == 0) {
        const unsigned char* b = (const unsigned char*)mp;
        int c3f = 0, cnz = 0;
        for (int k = 0; k < 512; k++) {
            if (b[4*k+3] == 0x3F) c3f++;
            if (b[4*k+1] | b[4*k+2]) cnz++;
        }
        mode = (c3f > 8) ? 2 : ((cnz > 8) ? 0 : 1);
    }
    __syncthreads();
    int m = mode;
    for (int idx = threadIdx.x; idx < T_*K_; idx += blockDim.x) {
        float v;
        if (m == 0)      v = ((const unsigned char*)mp)[idx] ? 1.f : 0.f;
        else if (m == 1) v = ((const int*)mp)[idx] ? 1.f : 0.f;
        else             v = (((const float*)mp)[idx] != 0.f) ? 1.f : 0.f;
        g_maskf[idx] = v;
    }
}

__global__ void proj_all(const float* __restrict__ image, const float* __restrict__ text,
                         const float* __restrict__ Wq, const float* __restrict__ Wk,
                         const float* __restrict__ Wv) {
    __shared__ float sA[64*33];
    __shared__ float sB[64*33];
    int bid = blockIdx.x;
    int which, h, rb;
    const float *X, *W;
    float* Y;
    if (bid < 392)      { which = 0; h = bid/49;       rb = bid%49;       X = image; W = Wq; Y = g_query; }
    else if (bid < 648) { which = 1; h = (bid-392)/32; rb = (bid-392)%32; X = text;  W = Wk; Y = g_key;   }
    else                { which = 2; h = (bid-648)/32; rb = (bid-648)%32; X = text;  W = Wv; Y = g_value; }
    int r0 = rb * 64;
    int tid = threadIdx.x;
    int tx = tid & 15, ty = tid >> 4;
    float acc[4][4] = {};
    #pragma unroll
    for (int kc = 0; kc < 64; kc += 32) {
        for (int idx = tid; idx < 2048; idx += 256) {
            int r = idx >> 5, kk = idx & 31;
            sA[r*33 + kk] = X[(r0 + r)*E_ + h*64 + kc + kk];
            sB[r*33 + kk] = W[r*64 + kc + kk];
        }
        __syncthreads();
        #pragma unroll
        for (int kk = 0; kk < 32; kk++) {
            float a[4], b[4];
            #pragma unroll
            for (int r = 0; r < 4; r++) a[r] = sA[(ty*4 + r)*33 + kk];
            #pragma unroll
            for (int c = 0; c < 4; c++) b[c] = sB[(tx*4 + c)*33 + kk];
            #pragma unroll
            for (int r = 0; r < 4; r++)
                #pragma unroll
                for (int c = 0; c < 4; c++) acc[r][c] += a[r] * b[c];
        }
        __syncthreads();
    }
    #pragma unroll
    for (int r = 0; r < 4; r++) {
        int row = r0 + ty*4 + r;
        long long obase;
        if (which == 0) { int i = row / Q_, q = row % Q_; obase = ((long long)(i*H_ + h)*Q_ + q)*64; }
        else            { int t = row >> 5, k = row & 31; obase = ((long long)(t*H_ + h)*K_ + k)*64; }
        #pragma unroll
        for (int c = 0; c < 4; c++)
            Y[obase + tx*4 + c] = acc[r][c];
    }
}

__global__ void kprep_kernel() {
    int th = blockIdx.x, tid = threadIdx.x;
    const float* Kg = g_key + (size_t)th*(K_*D_);
    unsigned char* B = g_kb + (size_t)th*BBUF;
    for (int idx = tid; idx < (K_*D_)/2; idx += 256) {
        int k = idx >> 5, d2 = (idx & 31)*2;
        float2 x = *(const float2*)&Kg[k*64 + d2];
        __nv_bfloat162 hi = __floats2bfloat162_rn(x.x, x.y);
        float2 hf = __bfloat1622float2(hi);
        __nv_bfloat162 lo = __floats2bfloat162_rn(x.x - hf.x, x.y - hf.y);
        *(__nv_bfloat162*)(B + (k*SA_ + d2)*2)       = hi;
        *(__nv_bfloat162*)(B + (k*SA_ + 64 + d2)*2)  = lo;
        *(__nv_bfloat162*)(B + (k*SA_ + 128 + d2)*2) = hi;
    }
}

__global__ void __launch_bounds__(NT_, 1)
attn_kernel(float* __restrict__ out, int wAttn, int wText) {
    extern __shared__ unsigned char smem[];
    unsigned sbase = smem_u32(smem);
    float* sE    = (float*)smem;
    float* sV    = (float*)(smem + V_OFF);
    float* sRinv = (float*)(smem + RINV_OFF);
    float* sMkA  = (float*)(smem + MK_OFF);
    float* sYO   = (float*)(smem + YO_OFF);
    float* sCA   = (float*)(smem + CA_OFF);
    float* sTA   = (float*)(smem + TA_OFF);
    float* sTB   = (float*)(smem + TB_OFF);
    float* sPE   = (float*)(smem + PE_OFF);
    float* sPA   = (float*)(smem + PA_OFF);

    int tid = threadIdx.x, lane = tid & 31, wid = tid >> 5;
    int bid = blockIdx.x;
    int u0 = (bid * NU_) / NCTA_;
    int u1 = ((bid + 1) * NU_) / NCTA_;

    // ---- initial stage of unit u0's B/V/mask into buffer 0 ----
    {
        int ihs = u0 >> 6, ts = u0 & 63, hs = ihs & 7;
        const float4* bs = (const float4*)(g_kb + (size_t)(ts*H_ + hs)*BBUF);
        float4* bd = (float4*)(smem + B_OFF);
        for (int idx = tid; idx < BBUF/16; idx += NT_) bd[idx] = bs[idx];
        const float4* vs = (const float4*)(g_value + (size_t)(ts*H_ + hs)*(K_*D_));
        float4* vd = (float4*)sV;
        for (int idx = tid; idx < (K_*D_)/4; idx += NT_) vd[idx] = vs[idx];
        if (tid < K_) {
            float m = g_maskf[ts*K_ + tid];
            sMkA[tid] = m;
            sYO[tid] = (m != 0.f) ? 0.f : -1e30f;
        }
    }
    __syncthreads();

    unsigned af[12][4];
    int curih = -1;
    const ull S2 = pack2(SC2_, SC2_);

    for (int u = u0; u < u1; u++) {
        int ih = u >> 6, t = u & 63;
        int h = ih & 7, i = ih >> 3;
        int p = (u - u0) & 1;

        // ---- (re)stage A + hoist fragments at ih boundary ----
        if (ih != curih) {
            unsigned* z = (unsigned*)smem;
            for (int idx = tid; idx < (MR_*SA_)/2; idx += NT_) z[idx] = 0u;
            __syncthreads();
            const float* Qg = g_query + (size_t)ih*(Q_*D_);
            unsigned char* A = smem;
            for (int idx = tid; idx < (Q_*D_)/2; idx += NT_) {
                int q = idx >> 5, d2 = (idx & 31)*2;
                float2 x = *(const float2*)&Qg[q*64 + d2];
                __nv_bfloat162 hi = __floats2bfloat162_rn(x.x, x.y);
                float2 hf = __bfloat1622float2(hi);
                __nv_bfloat162 lo = __floats2bfloat162_rn(x.x - hf.x, x.y - hf.y);
                *(__nv_bfloat162*)(A + (q*SA_ + d2)*2)       = hi;
                *(__nv_bfloat162*)(A + (q*SA_ + 64 + d2)*2)  = hi;
                *(__nv_bfloat162*)(A + (q*SA_ + 128 + d2)*2) = lo;
            }
            __syncthreads();
            if (wid < 13) {
                int lrow = lane & 15;
                int lcol = (lane < 16) ? 0 : 8;
                #pragma unroll
                for (int ks = 0; ks < 12; ks++) {
                    unsigned a = sbase + (unsigned)(((wid*16 + lrow)*SA_ + ks*16 + lcol)*2);
                    ldm_x4(a, af[ks][0], af[ks][1], af[ks][2], af[ks][3]);
                }
            }
            curih = ih;
        }

        long long tileOff = ((long long)(i*T_ + t)*H_ + h) * (Q_*K_);

        // ---- phase 1: MMA + in-register exp/rowsum/attn-store; warps 13-15 prefetch ----
        if (wid < 13) {
            unsigned sBb = sbase + B_OFF + (unsigned)(p*BBUF);
            int ln = lane & 15;
            int bn = ln & 7;
            int bc = (ln < 8) ? 0 : 8;
            int g = lane >> 2, q2 = lane & 3;
            float c[4][4] = {};
            #pragma unroll
            for (int ks = 0; ks < 12; ks++) {
                unsigned b0[4], b1[4];
                #pragma unroll
                for (int nt = 0; nt < 4; nt++) {
                    unsigned a = sBb + (unsigned)(((nt*8 + bn)*SA_ + ks*16 + bc)*2);
                    ldm_x2(a, b0[nt], b1[nt]);
                }
                #pragma unroll
                for (int nt = 0; nt < 4; nt++)
                    mma_bf16(c[nt], af[ks][0], af[ks][1], af[ks][2], af[ks][3], b0[nt], b1[nt]);
            }
            // exp in-register (mask folded via yoff), rowsum via quad shfl
            ull e0[4], e1[4];
            ull rs0 = pack2(0.f, 0.f), rs1 = pack2(0.f, 0.f);
            #pragma unroll
            for (int nt = 0; nt < 4; nt++) {
                ull yo = lds1(sbase + YO_OFF + (unsigned)(p*128 + (nt*8 + 2*q2)*4));
                ull v0 = fma2(pack2(c[nt][0], c[nt][1]), S2, yo);
                ull v1 = fma2(pack2(c[nt][2], c[nt][3]), S2, yo);
                e0[nt] = pack2(ex2(lo2(v0)), ex2(hi2(v0)));
                e1[nt] = pack2(ex2(lo2(v1)), ex2(hi2(v1)));
                rs0 = add2(rs0, e0[nt]);
                rs1 = add2(rs1, e1[nt]);
            }
            int r0 = wid*16 + g;
            // store e to sE for colsum/text passes
            #pragma unroll
            for (int nt = 0; nt < 4; nt++) {
                int col = nt*8 + 2*q2;
                *(float2*)&sE[r0*EST_ + col]       = make_float2(lo2(e0[nt]), hi2(e0[nt]));
                *(float2*)&sE[(r0 + 8)*EST_ + col] = make_float2(lo2(e1[nt]), hi2(e1[nt]));
            }
            float rsum0 = lo2(rs0) + hi2(rs0);
            float rsum1 = lo2(rs1) + hi2(rs1);
            rsum0 += __shfl_xor_sync(0xffffffffu, rsum0, 1);
            rsum0 += __shfl_xor_sync(0xffffffffu, rsum0, 2);
            rsum1 += __shfl_xor_sync(0xffffffffu, rsum1, 1);
            rsum1 += __shfl_xor_sync(0xffffffffu, rsum1, 2);
            float rinv0 = rcpa(rsum0), rinv1 = rcpa(rsum1);
            if (q2 == 0) { sRinv[r0] = rinv0; sRinv[r0 + 8] = rinv1; }
            if (wAttn) {
                float* ap = out + OUT_N + tileOff;
                ull rv0 = pack2(rinv0, rinv0), rv1 = pack2(rinv1, rinv1);
                if (r0 < Q_) {
                    #pragma unroll
                    for (int nt = 0; nt < 4; nt++)
                        stg2(ap + r0*K_ + nt*8 + 2*q2, mul2(e0[nt], rv0));
                }
                if (r0 + 8 < Q_) {
                    #pragma unroll
                    for (int nt = 0; nt < 4; nt++)
                        stg2(ap + (r0 + 8)*K_ + nt*8 + 2*q2, mul2(e1[nt], rv1));
                }
            }
        } else if (u + 1 < u1) {
            // warps 13-15: prefetch unit u+1
            int un = u + 1, ihn = un >> 6, tn = un & 63, hn = ihn & 7;
            int pn = p ^ 1;
            int idx0 = tid - 416;
            const float4* bs = (const float4*)(g_kb + (size_t)(tn*H_ + hn)*BBUF);
            float4* bd = (float4*)(smem + B_OFF + pn*BBUF);
            for (int idx = idx0; idx < BBUF/16; idx += 96) bd[idx] = bs[idx];
            const float4* vs = (const float4*)(g_value + (size_t)(tn*H_ + hn)*(K_*D_));
            float4* vd = (float4*)(sV + pn*(K_*D_));
            for (int idx = idx0; idx < (K_*D_)/4; idx += 96) vd[idx] = vs[idx];
            if (idx0 < K_) {
                float m = g_maskf[tn*K_ + idx0];
                sMkA[pn*32 + idx0] = m;
                sYO[pn*32 + idx0] = (m != 0.f) ? 0.f : -1e30f;
            }
        }
        __syncthreads();

        // ---- phase 2: column partials (warp sweeps rows, lane = k) ----
        {
            float pe = 0.f, pa = 0.f;
            for (int q = wid; q < Q_; q += 16) {
                float e = sE[q*EST_ + lane];
                pe += e;
                pa = fmaf(e, sRinv[q], pa);
            }
            sPE[wid*32 + lane] = pe;
            sPA[wid*32 + lane] = pa;
        }
        __syncthreads();
        if (tid < 32) {
            float pe = 0.f, pa = 0.f;
            #pragma unroll
            for (int w = 0; w < 16; w++) { pe += sPE[w*32 + tid]; pa += sPA[w*32 + tid]; }
            float m = sMkA[p*32 + tid];
            sCA[tid] = pa;
            sTA[tid] = (m != 0.f) ? rcpa(pe) : 0.f;
            sTB[tid] = (m != 0.f) ? 0.f : (1.f / (float)Q_);
        }
        __syncthreads();

        // ---- phase 3: text writeout + pooled ----
        if (wText) {
            float* tbase = out + OUT_N + (long long)ATT_N + tileOff;
            for (int idx = tid; idx < Q_*8; idx += NT_) {
                int q = idx >> 3, c = idx & 7;
                ull e0, e1, ta0, ta1, tb0, tb1;
                lds2(sbase + (unsigned)((q*EST_ + 4*c)*4), e0, e1);
                lds2(sbase + TA_OFF + (unsigned)(16*c), ta0, ta1);
                lds2(sbase + TB_OFF + (unsigned)(16*c), tb0, tb1);
                stg4(tbase + q*K_ + 4*c, fma2(e0, ta0, tb0), fma2(e1, ta1, tb1));
            }
        }
        if (tid < 64) {
            float a = 0.f;
            const float* vv = sV + p*(K_*D_);
            #pragma unroll
            for (int k = 0; k < 32; k++) a += sCA[k] * vv[k*D_ + tid];
            g_pooled[(long long)(i*T_ + t)*E_ + h*64 + tid] = a * (1.f / (float)Q_);
        }
        __syncthreads();
    }
}

__global__ void fc_kernel(const float* __restrict__ Wo, const float* __restrict__ bo,
                          float* __restrict__ out) {
    __shared__ float sA[64*33];
    __shared__ float sB[64*33];
    int rt = blockIdx.x * 64;
    int ct = blockIdx.y * 64;
    int tid = threadIdx.x;
    int tx = tid & 15, ty = tid >> 4;
    float acc[4][4] = {};
    float ra[8], rb[8];
    #pragma unroll
    for (int j = 0; j < 8; j++) {
        int idx = tid + j*256;
        int r = idx >> 5, kk = idx & 31;
        ra[j] = g_pooled[(rt + r)*E_ + kk];
        rb[j] = Wo[(ct + r)*E_ + kk];
    }
    for (int kc = 0; kc < E_; kc += 32) {
        #pragma unroll
        for (int j = 0; j < 8; j++) {
            int idx = tid + j*256;
            int r = idx >> 5, kk = idx & 31;
            sA[r*33 + kk] = ra[j];
            sB[r*33 + kk] = rb[j];
        }
        __syncthreads();
        if (kc + 32 < E_) {
            #pragma unroll
            for (int j = 0; j < 8; j++) {
                int idx = tid + j*256;
                int r = idx >> 5, kk = idx & 31;
                ra[j] = g_pooled[(rt + r)*E_ + kc + 32 + kk];
                rb[j] = Wo[(ct + r)*E_ + kc + 32 + kk];
            }
        }
        #pragma unroll
        for (int kk = 0; kk < 32; kk++) {
            float a[4], b[4];
            #pragma unroll
            for (int r = 0; r < 4; r++) a[r] = sA[(ty*4 + r)*33 + kk];
            #pragma unroll
            for (int c = 0; c < 4; c++) b[c] = sB[(tx*4 + c)*33 + kk];
            #pragma unroll
            for (int r = 0; r < 4; r++)
                #pragma unroll
                for (int c = 0; c < 4; c++) acc[r][c] += a[r] * b[c];
        }
        __syncthreads();
    }
    #pragma unroll
    for (int r = 0; r < 4; r++)
        #pragma unroll
        for (int c = 0; c < 4; c++)
            out[(rt + ty*4 + r)*E_ + ct + tx*4 + c] = acc[r][c] + bo[ct + tx*4 + c];
}

extern "C" void kernel_launch(void* const* d_in, const int* in_sizes, int n_in,
                              void* d_out, int out_size) {
    const float* image = (const float*)d_in[0];
    const float* text  = (const float*)d_in[1];
    const void*  mask  =                d_in[2];
    const float* Wq    = (const float*)d_in[3];
    const float* Wk    = (const float*)d_in[4];
    const float* Wv    = (const float*)d_in[5];
    const float* Wo    = (const float*)d_in[6];
    const float* bo    = (const float*)d_in[7];
    float* out = (float*)d_out;

    cudaFuncSetAttribute(attn_kernel, cudaFuncAttributeMaxDynamicSharedMemorySize, SMEM_ATTN);

    mask_kernel<<<1, 256>>>(mask);
    proj_all<<<904, 256>>>(image, text, Wq, Wk, Wv);
    kprep_kernel<<<T_*H_, 256>>>();

    int wAttn = out_size >= (OUT_N + ATT_N);
    int wText = out_size >= (OUT_N + 2*ATT_N);
    attn_kernel<<<NCTA_, NT_, SMEM_ATTN>>>(out, wAttn, wText);

    if (out_size >= OUT_N)
        fc_kernel<<<dim3(16, 8), 256>>>(Wo, bo, out);
}

// round 11
// speedup vs baseline: 1.4572x; 1.0294x over previous
#include <cuda_runtime.h>
#include <cuda_bf16.h>
#include <math.h>
#include <cstdint>

#define I_ 16
#define T_ 64
#define Q_ 196
#define K_ 32
#define E_ 512
#define H_ 8
#define D_ 64
#define NT_ 512
#define NCTA_ 148
#define NU_ (I_*H_*T_)

#define OUT_N   (I_*T_*E_)
#define ATT_N   (I_*T_*H_*Q_*K_)
#define SC2_    ((float)(0.044194173824159216*1.4426950408889634))

#define SA_  200
#define MR_  208
#define BBUF (K_*SA_*2)                 // 12800

#define B_OFF    83200
#define V_OFF    (B_OFF + 2*BBUF)       // 108800
#define RINV_OFF (V_OFF + 2*8192)       // 125184
#define MK_OFF   126016
#define YO_OFF   126272
#define CA_OFF   126528
#define TA_OFF   126656
#define TB_OFF   126784
#define PE_OFF   126912                 // 13*32 floats (pad to 2048B)
#define PA_OFF   128960
#define SMEM_ATTN 131008

typedef unsigned long long ull;

__device__ float g_query[I_*H_*Q_*D_];
__device__ float g_key  [T_*H_*K_*D_];
__device__ float g_value[T_*H_*K_*D_];
__device__ float g_pooled[I_*T_*E_];
__device__ float g_maskf[T_*K_];
__device__ unsigned char g_kb[(size_t)T_*H_*BBUF];

__device__ __forceinline__ unsigned smem_u32(const void* p) {
    unsigned a;
    asm("{ .reg .u64 t; cvta.to.shared.u64 t, %1; cvt.u32.u64 %0, t; }" : "=r"(a) : "l"(p));
    return a;
}
__device__ __forceinline__ ull fma2(ull a, ull b, ull c) {
    ull d; asm("fma.rn.f32x2 %0, %1, %2, %3;" : "=l"(d) : "l"(a), "l"(b), "l"(c)); return d;
}
__device__ __forceinline__ ull mul2(ull a, ull b) {
    ull d; asm("mul.rn.f32x2 %0, %1, %2;" : "=l"(d) : "l"(a), "l"(b)); return d;
}
__device__ __forceinline__ ull add2(ull a, ull b) {
    ull d; asm("add.rn.f32x2 %0, %1, %2;" : "=l"(d) : "l"(a), "l"(b)); return d;
}
__device__ __forceinline__ ull pack2(float x, float y) {
    ull d; asm("mov.b64 %0, {%1, %2};" : "=l"(d) : "f"(x), "f"(y)); return d;
}
__device__ __forceinline__ float lo2(ull a) { return __uint_as_float((unsigned)a); }
__device__ __forceinline__ float hi2(ull a) { return __uint_as_float((unsigned)(a >> 32)); }
__device__ __forceinline__ float ex2(float x) {
    float y; asm("ex2.approx.f32 %0, %1;" : "=f"(y) : "f"(x)); return y;
}
__device__ __forceinline__ float rcpa(float x) {
    float y; asm("rcp.approx.f32 %0, %1;" : "=f"(y) : "f"(x)); return y;
}
__device__ __forceinline__ ull lds1(unsigned a) {
    ull x; asm volatile("ld.shared.b64 %0, [%1];" : "=l"(x) : "r"(a)); return x;
}
__device__ __forceinline__ void stg2(float* p, ull v) {
    asm volatile("{ .reg .f32 x,y; mov.b64 {x,y}, %1; st.global.v2.f32 [%0], {x,y}; }"
                 :: "l"(p), "l"(v) : "memory");
}
__device__ __forceinline__ void ldm_x4(unsigned a, unsigned& r0, unsigned& r1,
                                       unsigned& r2, unsigned& r3) {
    asm volatile("ldmatrix.sync.aligned.m8n8.x4.shared.b16 {%0,%1,%2,%3}, [%4];"
                 : "=r"(r0), "=r"(r1), "=r"(r2), "=r"(r3) : "r"(a));
}
__device__ __forceinline__ void ldm_x2(unsigned a, unsigned& r0, unsigned& r1) {
    asm volatile("ldmatrix.sync.aligned.m8n8.x2.shared.b16 {%0,%1}, [%2];"
                 : "=r"(r0), "=r"(r1) : "r"(a));
}
__device__ __forceinline__ void mma_bf16(float* c, unsigned a0, unsigned a1, unsigned a2,
                                         unsigned a3, unsigned b0, unsigned b1) {
    asm volatile("mma.sync.aligned.m16n8k16.row.col.f32.bf16.bf16.f32 "
                 "{%0,%1,%2,%3}, {%4,%5,%6,%7}, {%8,%9}, {%0,%1,%2,%3};"
                 : "+f"(c[0]), "+f"(c[1]), "+f"(c[2]), "+f"(c[3])
                 : "r"(a0), "r"(a1), "r"(a2), "r"(a3), "r"(b0), "r"(b1));
}

__global__ void mask_kernel(const void* mp) {
    __shared__ int mode;
    if (threadIdx.x == 0) {
        const unsigned char* b = (const unsigned char*)mp;
        int c3f = 0, cnz = 0;
        for (int k = 0; k < 512; k++) {
            if (b[4*k+3] == 0x3F) c3f++;
            if (b[4*k+1] | b[4*k+2]) cnz++;
        }
        mode = (c3f > 8) ? 2 : ((cnz > 8) ? 0 : 1);
    }
    __syncthreads();
    int m = mode;
    for (int idx = threadIdx.x; idx < T_*K_; idx += blockDim.x) {
        float v;
        if (m == 0)      v = ((const unsigned char*)mp)[idx] ? 1.f : 0.f;
        else if (m == 1) v = ((const int*)mp)[idx] ? 1.f : 0.f;
        else             v = (((const float*)mp)[idx] != 0.f) ? 1.f : 0.f;
        g_maskf[idx] = v;
    }
}

__global__ void proj_all(const float* __restrict__ image, const float* __restrict__ text,
                         const float* __restrict__ Wq, const float* __restrict__ Wk,
                         const float* __restrict__ Wv) {
    __shared__ float sA[64*33];
    __shared__ float sB[64*33];
    int bid = blockIdx.x;
    int which, h, rb;
    const float *X, *W;
    float* Y;
    if (bid < 392)      { which = 0; h = bid/49;       rb = bid%49;       X = image; W = Wq; Y = g_query; }
    else if (bid < 648) { which = 1; h = (bid-392)/32; rb = (bid-392)%32; X = text;  W = Wk; Y = g_key;   }
    else                { which = 2; h = (bid-648)/32; rb = (bid-648)%32; X = text;  W = Wv; Y = g_value; }
    int r0 = rb * 64;
    int tid = threadIdx.x;
    int tx = tid & 15, ty = tid >> 4;
    float acc[4][4] = {};
    #pragma unroll
    for (int kc = 0; kc < 64; kc += 32) {
        for (int idx = tid; idx < 2048; idx += 256) {
            int r = idx >> 5, kk = idx & 31;
            sA[r*33 + kk] = X[(r0 + r)*E_ + h*64 + kc + kk];
            sB[r*33 + kk] = W[r*64 + kc + kk];
        }
        __syncthreads();
        #pragma unroll
        for (int kk = 0; kk < 32; kk++) {
            float a[4], b[4];
            #pragma unroll
            for (int r = 0; r < 4; r++) a[r] = sA[(ty*4 + r)*33 + kk];
            #pragma unroll
            for (int c = 0; c < 4; c++) b[c] = sB[(tx*4 + c)*33 + kk];
            #pragma unroll
            for (int r = 0; r < 4; r++)
                #pragma unroll
                for (int c = 0; c < 4; c++) acc[r][c] += a[r] * b[c];
        }
        __syncthreads();
    }
    #pragma unroll
    for (int r = 0; r < 4; r++) {
        int row = r0 + ty*4 + r;
        long long obase;
        if (which == 0) { int i = row / Q_, q = row % Q_; obase = ((long long)(i*H_ + h)*Q_ + q)*64; }
        else            { int t = row >> 5, k = row & 31; obase = ((long long)(t*H_ + h)*K_ + k)*64; }
        #pragma unroll
        for (int c = 0; c < 4; c++)
            Y[obase + tx*4 + c] = acc[r][c];
    }
}

__global__ void kprep_kernel() {
    int th = blockIdx.x, tid = threadIdx.x;
    const float* Kg = g_key + (size_t)th*(K_*D_);
    unsigned char* B = g_kb + (size_t)th*BBUF;
    for (int idx = tid; idx < (K_*D_)/2; idx += 256) {
        int k = idx >> 5, d2 = (idx & 31)*2;
        float2 x = *(const float2*)&Kg[k*64 + d2];
        __nv_bfloat162 hi = __floats2bfloat162_rn(x.x, x.y);
        float2 hf = __bfloat1622float2(hi);
        __nv_bfloat162 lo = __floats2bfloat162_rn(x.x - hf.x, x.y - hf.y);
        *(__nv_bfloat162*)(B + (k*SA_ + d2)*2)       = hi;
        *(__nv_bfloat162*)(B + (k*SA_ + 64 + d2)*2)  = lo;
        *(__nv_bfloat162*)(B + (k*SA_ + 128 + d2)*2) = hi;
    }
}

__global__ void __launch_bounds__(NT_, 1)
attn_kernel(float* __restrict__ out, int wAttn, int wText) {
    extern __shared__ unsigned char smem[];
    unsigned sbase = smem_u32(smem);
    float* sV    = (float*)(smem + V_OFF);
    float* sRinv = (float*)(smem + RINV_OFF);
    float* sMkA  = (float*)(smem + MK_OFF);
    float* sYO   = (float*)(smem + YO_OFF);
    float* sCA   = (float*)(smem + CA_OFF);
    float* sTA   = (float*)(smem + TA_OFF);
    float* sTB   = (float*)(smem + TB_OFF);
    float* sPE   = (float*)(smem + PE_OFF);
    float* sPA   = (float*)(smem + PA_OFF);

    int tid = threadIdx.x, lane = tid & 31, wid = tid >> 5;
    int bid = blockIdx.x;
    int u0 = (bid * NU_) / NCTA_;
    int u1 = ((bid + 1) * NU_) / NCTA_;

    // ---- stage unit u0's B/V/mask into buffer 0 ----
    {
        int ihs = u0 >> 6, ts = u0 & 63, hs = ihs & 7;
        const float4* bs = (const float4*)(g_kb + (size_t)(ts*H_ + hs)*BBUF);
        float4* bd = (float4*)(smem + B_OFF);
        for (int idx = tid; idx < BBUF/16; idx += NT_) bd[idx] = bs[idx];
        const float4* vs = (const float4*)(g_value + (size_t)(ts*H_ + hs)*(K_*D_));
        float4* vd = (float4*)sV;
        for (int idx = tid; idx < (K_*D_)/4; idx += NT_) vd[idx] = vs[idx];
        if (tid < K_) {
            float m = g_maskf[ts*K_ + tid];
            sMkA[tid] = m;
            sYO[tid] = (m != 0.f) ? 0.f : -1e30f;
        }
    }
    __syncthreads();

    unsigned af[12][4];
    int curih = -1;
    const ull S2 = pack2(SC2_, SC2_);
    int g = lane >> 2, q2 = lane & 3;

    for (int u = u0; u < u1; u++) {
        int ih = u >> 6, t = u & 63;
        int h = ih & 7, i = ih >> 3;
        int p = (u - u0) & 1;

        if (ih != curih) {
            unsigned* z = (unsigned*)smem;
            for (int idx = tid; idx < (MR_*SA_)/2; idx += NT_) z[idx] = 0u;
            __syncthreads();
            const float* Qg = g_query + (size_t)ih*(Q_*D_);
            unsigned char* A = smem;
            for (int idx = tid; idx < (Q_*D_)/2; idx += NT_) {
                int q = idx >> 5, d2 = (idx & 31)*2;
                float2 x = *(const float2*)&Qg[q*64 + d2];
                __nv_bfloat162 hi = __floats2bfloat162_rn(x.x, x.y);
                float2 hf = __bfloat1622float2(hi);
                __nv_bfloat162 lo = __floats2bfloat162_rn(x.x - hf.x, x.y - hf.y);
                *(__nv_bfloat162*)(A + (q*SA_ + d2)*2)       = hi;
                *(__nv_bfloat162*)(A + (q*SA_ + 64 + d2)*2)  = hi;
                *(__nv_bfloat162*)(A + (q*SA_ + 128 + d2)*2) = lo;
            }
            __syncthreads();
            if (wid < 13) {
                int lrow = lane & 15;
                int lcol = (lane < 16) ? 0 : 8;
                #pragma unroll
                for (int ks = 0; ks < 12; ks++) {
                    unsigned a = sbase + (unsigned)(((wid*16 + lrow)*SA_ + ks*16 + lcol)*2);
                    ldm_x4(a, af[ks][0], af[ks][1], af[ks][2], af[ks][3]);
                }
            }
            curih = ih;
        }

        long long tileOff = ((long long)(i*T_ + t)*H_ + h) * (Q_*K_);
        ull e0[4], e1[4];
        int r0 = wid*16 + g;

        // ---- phase 1: MMA + exp + rowsum + attn store + in-register col partials ----
        if (wid < 13) {
            unsigned sBb = sbase + B_OFF + (unsigned)(p*BBUF);
            int ln = lane & 15;
            int bn = ln & 7;
            int bc = (ln < 8) ? 0 : 8;
            float c[4][4] = {};
            #pragma unroll
            for (int ks = 0; ks < 12; ks++) {
                unsigned b0[4], b1[4];
                #pragma unroll
                for (int nt = 0; nt < 4; nt++) {
                    unsigned a = sBb + (unsigned)(((nt*8 + bn)*SA_ + ks*16 + bc)*2);
                    ldm_x2(a, b0[nt], b1[nt]);
                }
                #pragma unroll
                for (int nt = 0; nt < 4; nt++)
                    mma_bf16(c[nt], af[ks][0], af[ks][1], af[ks][2], af[ks][3], b0[nt], b1[nt]);
            }
            ull rs0 = pack2(0.f, 0.f), rs1 = pack2(0.f, 0.f);
            #pragma unroll
            for (int nt = 0; nt < 4; nt++) {
                ull yo = lds1(sbase + YO_OFF + (unsigned)(p*128 + (nt*8 + 2*q2)*4));
                ull v0 = fma2(pack2(c[nt][0], c[nt][1]), S2, yo);
                ull v1 = fma2(pack2(c[nt][2], c[nt][3]), S2, yo);
                e0[nt] = pack2(ex2(lo2(v0)), ex2(hi2(v0)));
                e1[nt] = pack2(ex2(lo2(v1)), ex2(hi2(v1)));
                rs0 = add2(rs0, e0[nt]);
                rs1 = add2(rs1, e1[nt]);
            }
            float rsum0 = lo2(rs0) + hi2(rs0);
            float rsum1 = lo2(rs1) + hi2(rs1);
            rsum0 += __shfl_xor_sync(0xffffffffu, rsum0, 1);
            rsum0 += __shfl_xor_sync(0xffffffffu, rsum0, 2);
            rsum1 += __shfl_xor_sync(0xffffffffu, rsum1, 1);
            rsum1 += __shfl_xor_sync(0xffffffffu, rsum1, 2);
            float rinv0 = rcpa(rsum0), rinv1 = rcpa(rsum1);
            if (q2 == 0) { sRinv[r0] = rinv0; sRinv[r0 + 8] = rinv1; }
            if (wAttn) {
                float* ap = out + OUT_N + tileOff;
                ull rv0 = pack2(rinv0, rinv0), rv1 = pack2(rinv1, rinv1);
                if (r0 < Q_) {
                    #pragma unroll
                    for (int nt = 0; nt < 4; nt++)
                        stg2(ap + r0*K_ + nt*8 + 2*q2, mul2(e0[nt], rv0));
                }
                if (r0 + 8 < Q_) {
                    #pragma unroll
                    for (int nt = 0; nt < 4; nt++)
                        stg2(ap + (r0 + 8)*K_ + nt*8 + 2*q2, mul2(e1[nt], rv1));
                }
            }
            // in-register column partials (mask padding rows 196..207)
            float m0f = (r0 < Q_) ? 1.f : 0.f;
            float m1f = (r0 + 8 < Q_) ? 1.f : 0.f;
            ull M0 = pack2(m0f, m0f), M1 = pack2(m1f, m1f);
            ull rv0p = pack2(rinv0*m0f, rinv0*m0f);
            ull rv1p = pack2(rinv1*m1f, rinv1*m1f);
            #pragma unroll
            for (int nt = 0; nt < 4; nt++) {
                ull pe = fma2(e1[nt], M1, mul2(e0[nt], M0));
                ull pa = fma2(e1[nt], rv1p, mul2(e0[nt], rv0p));
                float pex = lo2(pe), pey = hi2(pe), pax = lo2(pa), pay = hi2(pa);
                #pragma unroll
                for (int o = 4; o <= 16; o <<= 1) {
                    pex += __shfl_xor_sync(0xffffffffu, pex, o);
                    pey += __shfl_xor_sync(0xffffffffu, pey, o);
                    pax += __shfl_xor_sync(0xffffffffu, pax, o);
                    pay += __shfl_xor_sync(0xffffffffu, pay, o);
                }
                if (lane < 4) {
                    int col = nt*8 + 2*lane;
                    sPE[wid*32 + col] = pex; sPE[wid*32 + col + 1] = pey;
                    sPA[wid*32 + col] = pax; sPA[wid*32 + col + 1] = pay;
                }
            }
        } else if (u + 1 < u1) {
            int un = u + 1, ihn = un >> 6, tn = un & 63, hn = ihn & 7;
            int pn = p ^ 1;
            int idx0 = tid - 416;
            const float4* bs = (const float4*)(g_kb + (size_t)(tn*H_ + hn)*BBUF);
            float4* bd = (float4*)(smem + B_OFF + pn*BBUF);
            for (int idx = idx0; idx < BBUF/16; idx += 96) bd[idx] = bs[idx];
            const float4* vs = (const float4*)(g_value + (size_t)(tn*H_ + hn)*(K_*D_));
            float4* vd = (float4*)(sV + pn*(K_*D_));
            for (int idx = idx0; idx < (K_*D_)/4; idx += 96) vd[idx] = vs[idx];
            if (idx0 < K_) {
                float m = g_maskf[tn*K_ + idx0];
                sMkA[pn*32 + idx0] = m;
                sYO[pn*32 + idx0] = (m != 0.f) ? 0.f : -1e30f;
            }
        }
        __syncthreads();

        // ---- phase 2: reduce 13 warp partials -> colsums ----
        if (tid < 32) {
            float pe = 0.f, pa = 0.f;
            #pragma unroll
            for (int w = 0; w < 13; w++) { pe += sPE[w*32 + tid]; pa += sPA[w*32 + tid]; }
            float m = sMkA[p*32 + tid];
            sCA[tid] = pa;
            sTA[tid] = (m != 0.f) ? rcpa(pe) : 0.f;
            sTB[tid] = (m != 0.f) ? 0.f : (1.f / (float)Q_);
        }
        __syncthreads();

        // ---- phase 3: text from registers + pooled ----
        if (wText && wid < 13) {
            float* tbase = out + OUT_N + (long long)ATT_N + tileOff;
            #pragma unroll
            for (int nt = 0; nt < 4; nt++) {
                int col = nt*8 + 2*q2;
                ull ta = lds1(sbase + TA_OFF + (unsigned)(col*4));
                ull tb = lds1(sbase + TB_OFF + (unsigned)(col*4));
                if (r0 < Q_)     stg2(tbase + r0*K_ + col,       fma2(e0[nt], ta, tb));
                if (r0 + 8 < Q_) stg2(tbase + (r0 + 8)*K_ + col, fma2(e1[nt], ta, tb));
            }
        }
        if (tid < 64) {
            float a = 0.f;
            const float* vv = sV + p*(K_*D_);
            #pragma unroll
            for (int k = 0; k < 32; k++) a += sCA[k] * vv[k*D_ + tid];
            g_pooled[(long long)(i*T_ + t)*E_ + h*64 + tid] = a * (1.f / (float)Q_);
        }
        __syncthreads();
    }
}

__global__ void fc_kernel(const float* __restrict__ Wo, const float* __restrict__ bo,
                          float* __restrict__ out) {
    __shared__ float sA[64*33];
    __shared__ float sB[64*33];
    int rt = blockIdx.x * 64;
    int ct = blockIdx.y * 64;
    int tid = threadIdx.x;
    int tx = tid & 15, ty = tid >> 4;
    float acc[4][4] = {};
    float ra[8], rb[8];
    #pragma unroll
    for (int j = 0; j < 8; j++) {
        int idx = tid + j*256;
        int r = idx >> 5, kk = idx & 31;
        ra[j] = g_pooled[(rt + r)*E_ + kk];
        rb[j] = Wo[(ct + r)*E_ + kk];
    }
    for (int kc = 0; kc < E_; kc += 32) {
        #pragma unroll
        for (int j = 0; j < 8; j++) {
            int idx = tid + j*256;
            int r = idx >> 5, kk = idx & 31;
            sA[r*33 + kk] = ra[j];
            sB[r*33 + kk] = rb[j];
        }
        __syncthreads();
        if (kc + 32 < E_) {
            #pragma unroll
            for (int j = 0; j < 8; j++) {
                int idx = tid + j*256;
                int r = idx >> 5, kk = idx & 31;
                ra[j] = g_pooled[(rt + r)*E_ + kc + 32 + kk];
                rb[j] = Wo[(ct + r)*E_ + kc + 32 + kk];
            }
        }
        #pragma unroll
        for (int kk = 0; kk < 32; kk++) {
            float a[4], b[4];
            #pragma unroll
            for (int r = 0; r < 4; r++) a[r] = sA[(ty*4 + r)*33 + kk];
            #pragma unroll
            for (int c = 0; c < 4; c++) b[c] = sB[(tx*4 + c)*33 + kk];
            #pragma unroll
            for (int r = 0; r < 4; r++)
                #pragma unroll
                for (int c = 0; c < 4; c++) acc[r][c] += a[r] * b[c];
        }
        __syncthreads();
    }
    #pragma unroll
    for (int r = 0; r < 4; r++)
        #pragma unroll
        for (int c = 0; c < 4; c++)
            out[(rt + ty*4 + r)*E_ + ct + tx*4 + c] = acc[r][c] + bo[ct + tx*4 + c];
}

extern "C" void kernel_launch(void* const* d_in, const int* in_sizes, int n_in,
                              void* d_out, int out_size) {
    const float* image = (const float*)d_in[0];
    const float* text  = (const float*)d_in[1];
    const void*  mask  =                d_in[2];
    const float* Wq    = (const float*)d_in[3];
    const float* Wk    = (const float*)d_in[4];
    const float* Wv    = (const float*)d_in[5];
    const float* Wo    = (const float*)d_in[6];
    const float* bo    = (const float*)d_in[7];
    float* out = (float*)d_out;

    cudaFuncSetAttribute(attn_kernel, cudaFuncAttributeMaxDynamicSharedMemorySize, SMEM_ATTN);

    mask_kernel<<<1, 256>>>(mask);
    proj_all<<<904, 256>>>(image, text, Wq, Wk, Wv);
    kprep_kernel<<<T_*H_, 256>>>();

    int wAttn = out_size >= (OUT_N + ATT_N);
    int wText = out_size >= (OUT_N + 2*ATT_N);
    attn_kernel<<<NCTA_, NT_, SMEM_ATTN>>>(out, wAttn, wText);

    if (out_size >= OUT_N)
        fc_kernel<<<dim3(16, 8), 256>>>(Wo, bo, out);
}

// round 12
// speedup vs baseline: 1.8963x; 1.3013x over previous
#include <cuda_runtime.h>
#include <cuda_bf16.h>
#include <math.h>
#include <cstdint>

#define I_ 16
#define T_ 64
#define Q_ 196
#define K_ 32
#define E_ 512
#define H_ 8
#define D_ 64
#define NT_ 512
#define NCTA_ 148
#define NU_ (I_*H_*T_)

#define OUT_N   (I_*T_*E_)
#define ATT_N   (I_*T_*H_*Q_*K_)
#define SC2_    ((float)(0.044194173824159216*1.4426950408889634))

#define SA_  200
#define MR_  208
#define BBUF (K_*SA_*2)                 // 12800
#define VBUF (K_*D_*4)                  // 8192

#define YO_OFF   83200                  // A region [0,83200)
#define B_OFF    91392
#define V_OFF    116992
#define PE_OFF   133376
#define PA_OFF   135424
#define SMEM_ATTN 137472

typedef unsigned long long ull;

__device__ float g_query[I_*H_*Q_*D_];
__device__ float g_key  [T_*H_*K_*D_];
__device__ float g_value[T_*H_*K_*D_];
__device__ float g_pooled[I_*T_*E_];
__device__ float g_maskf[T_*K_];
__device__ unsigned char g_kb[(size_t)T_*H_*BBUF];

__device__ __forceinline__ unsigned smem_u32(const void* p) {
    unsigned a;
    asm("{ .reg .u64 t; cvta.to.shared.u64 t, %1; cvt.u32.u64 %0, t; }" : "=r"(a) : "l"(p));
    return a;
}
__device__ __forceinline__ ull fma2(ull a, ull b, ull c) {
    ull d; asm("fma.rn.f32x2 %0, %1, %2, %3;" : "=l"(d) : "l"(a), "l"(b), "l"(c)); return d;
}
__device__ __forceinline__ ull mul2(ull a, ull b) {
    ull d; asm("mul.rn.f32x2 %0, %1, %2;" : "=l"(d) : "l"(a), "l"(b)); return d;
}
__device__ __forceinline__ ull add2(ull a, ull b) {
    ull d; asm("add.rn.f32x2 %0, %1, %2;" : "=l"(d) : "l"(a), "l"(b)); return d;
}
__device__ __forceinline__ ull pack2(float x, float y) {
    ull d; asm("mov.b64 %0, {%1, %2};" : "=l"(d) : "f"(x), "f"(y)); return d;
}
__device__ __forceinline__ float lo2(ull a) { return __uint_as_float((unsigned)a); }
__device__ __forceinline__ float hi2(ull a) { return __uint_as_float((unsigned)(a >> 32)); }
__device__ __forceinline__ float ex2(float x) {
    float y; asm("ex2.approx.f32 %0, %1;" : "=f"(y) : "f"(x)); return y;
}
__device__ __forceinline__ float rcpa(float x) {
    float y; asm("rcp.approx.f32 %0, %1;" : "=f"(y) : "f"(x)); return y;
}
__device__ __forceinline__ ull lds1(unsigned a) {
    ull x; asm volatile("ld.shared.b64 %0, [%1];" : "=l"(x) : "r"(a)); return x;
}
__device__ __forceinline__ void stg2(float* p, ull v) {
    asm volatile("{ .reg .f32 x,y; mov.b64 {x,y}, %1; st.global.v2.f32 [%0], {x,y}; }"
                 :: "l"(p), "l"(v) : "memory");
}
__device__ __forceinline__ void cpa16(unsigned dst, const void* src) {
    asm volatile("cp.async.cg.shared.global [%0], [%1], 16;" :: "r"(dst), "l"(src) : "memory");
}
#define CPA_COMMIT() asm volatile("cp.async.commit_group;" ::: "memory")
#define CPA_WAIT()   asm volatile("cp.async.wait_group 0;" ::: "memory")
__device__ __forceinline__ void ldm_x4(unsigned a, unsigned& r0, unsigned& r1,
                                       unsigned& r2, unsigned& r3) {
    asm volatile("ldmatrix.sync.aligned.m8n8.x4.shared.b16 {%0,%1,%2,%3}, [%4];"
                 : "=r"(r0), "=r"(r1), "=r"(r2), "=r"(r3) : "r"(a));
}
__device__ __forceinline__ void ldm_x2(unsigned a, unsigned& r0, unsigned& r1) {
    asm volatile("ldmatrix.sync.aligned.m8n8.x2.shared.b16 {%0,%1}, [%2];"
                 : "=r"(r0), "=r"(r1) : "r"(a));
}
__device__ __forceinline__ void mma_bf16(float* c, unsigned a0, unsigned a1, unsigned a2,
                                         unsigned a3, unsigned b0, unsigned b1) {
    asm volatile("mma.sync.aligned.m16n8k16.row.col.f32.bf16.bf16.f32 "
                 "{%0,%1,%2,%3}, {%4,%5,%6,%7}, {%8,%9}, {%0,%1,%2,%3};"
                 : "+f"(c[0]), "+f"(c[1]), "+f"(c[2]), "+f"(c[3])
                 : "r"(a0), "r"(a1), "r"(a2), "r"(a3), "r"(b0), "r"(b1));
}

__global__ void mask_kernel(const void* mp) {
    __shared__ int mode;
    if (threadIdx.x == 0) {
        const unsigned char* b = (const unsigned char*)mp;
        int c3f = 0, cnz = 0;
        for (int k = 0; k < 512; k++) {
            if (b[4*k+3] == 0x3F) c3f++;
            if (b[4*k+1] | b[4*k+2]) cnz++;
        }
        mode = (c3f > 8) ? 2 : ((cnz > 8) ? 0 : 1);
    }
    __syncthreads();
    int m = mode;
    for (int idx = threadIdx.x; idx < T_*K_; idx += blockDim.x) {
        float v;
        if (m == 0)      v = ((const unsigned char*)mp)[idx] ? 1.f : 0.f;
        else if (m == 1) v = ((const int*)mp)[idx] ? 1.f : 0.f;
        else             v = (((const float*)mp)[idx] != 0.f) ? 1.f : 0.f;
        g_maskf[idx] = v;
    }
}

__global__ void proj_all(const float* __restrict__ image, const float* __restrict__ text,
                         const float* __restrict__ Wq, const float* __restrict__ Wk,
                         const float* __restrict__ Wv) {
    __shared__ float sA[64*33];
    __shared__ float sB[64*33];
    int bid = blockIdx.x;
    int which, h, rb;
    const float *X, *W;
    float* Y;
    if (bid < 392)      { which = 0; h = bid/49;       rb = bid%49;       X = image; W = Wq; Y = g_query; }
    else if (bid < 648) { which = 1; h = (bid-392)/32; rb = (bid-392)%32; X = text;  W = Wk; Y = g_key;   }
    else                { which = 2; h = (bid-648)/32; rb = (bid-648)%32; X = text;  W = Wv; Y = g_value; }
    int r0 = rb * 64;
    int tid = threadIdx.x;
    int tx = tid & 15, ty = tid >> 4;
    float acc[4][4] = {};
    #pragma unroll
    for (int kc = 0; kc < 64; kc += 32) {
        for (int idx = tid; idx < 2048; idx += 256) {
            int r = idx >> 5, kk = idx & 31;
            sA[r*33 + kk] = X[(r0 + r)*E_ + h*64 + kc + kk];
            sB[r*33 + kk] = W[r*64 + kc + kk];
        }
        __syncthreads();
        #pragma unroll
        for (int kk = 0; kk < 32; kk++) {
            float a[4], b[4];
            #pragma unroll
            for (int r = 0; r < 4; r++) a[r] = sA[(ty*4 + r)*33 + kk];
            #pragma unroll
            for (int c = 0; c < 4; c++) b[c] = sB[(tx*4 + c)*33 + kk];
            #pragma unroll
            for (int r = 0; r < 4; r++)
                #pragma unroll
                for (int c = 0; c < 4; c++) acc[r][c] += a[r] * b[c];
        }
        __syncthreads();
    }
    #pragma unroll
    for (int r = 0; r < 4; r++) {
        int row = r0 + ty*4 + r;
        long long obase;
        if (which == 0) { int i = row / Q_, q = row % Q_; obase = ((long long)(i*H_ + h)*Q_ + q)*64; }
        else            { int t = row >> 5, k = row & 31; obase = ((long long)(t*H_ + h)*K_ + k)*64; }
        #pragma unroll
        for (int c = 0; c < 4; c++)
            Y[obase + tx*4 + c] = acc[r][c];
    }
}

__global__ void kprep_kernel() {
    int th = blockIdx.x, tid = threadIdx.x;
    const float* Kg = g_key + (size_t)th*(K_*D_);
    unsigned char* B = g_kb + (size_t)th*BBUF;
    for (int idx = tid; idx < (K_*D_)/2; idx += 256) {
        int k = idx >> 5, d2 = (idx & 31)*2;
        float2 x = *(const float2*)&Kg[k*64 + d2];
        __nv_bfloat162 hi = __floats2bfloat162_rn(x.x, x.y);
        float2 hf = __bfloat1622float2(hi);
        __nv_bfloat162 lo = __floats2bfloat162_rn(x.x - hf.x, x.y - hf.y);
        *(__nv_bfloat162*)(B + (k*SA_ + d2)*2)       = hi;
        *(__nv_bfloat162*)(B + (k*SA_ + 64 + d2)*2)  = lo;
        *(__nv_bfloat162*)(B + (k*SA_ + 128 + d2)*2) = hi;
    }
}

__global__ void __launch_bounds__(NT_, 1)
attn_kernel(float* __restrict__ out, int wAttn, int wText) {
    extern __shared__ unsigned char smem[];
    unsigned sbase = smem_u32(smem);
    float* sYO = (float*)(smem + YO_OFF);
    float* sV  = (float*)(smem + V_OFF);
    float* sPE = (float*)(smem + PE_OFF);
    float* sPA = (float*)(smem + PA_OFF);

    int tid = threadIdx.x, lane = tid & 31, wid = tid >> 5;
    int bid = blockIdx.x;
    int u0 = (bid * NU_) / NCTA_;
    int u1 = ((bid + 1) * NU_) / NCTA_;

    // ---- prologue: yoff table + stage unit u0's B/V ----
    for (int idx = tid; idx < T_*K_; idx += NT_) {
        float m = g_maskf[idx];
        sYO[idx] = (m != 0.f) ? 0.f : -1e30f;
    }
    {
        int ihs = u0 >> 6, ts = u0 & 63, hs = ihs & 7;
        const float4* bs = (const float4*)(g_kb + (size_t)(ts*H_ + hs)*BBUF);
        float4* bd = (float4*)(smem + B_OFF);
        for (int idx = tid; idx < BBUF/16; idx += NT_) bd[idx] = bs[idx];
        const float4* vs = (const float4*)(g_value + (size_t)(ts*H_ + hs)*(K_*D_));
        float4* vd = (float4*)sV;
        for (int idx = tid; idx < (K_*D_)/4; idx += NT_) vd[idx] = vs[idx];
    }
    __syncthreads();

    unsigned af[12][4];
    int curih = -1;
    const ull S2 = pack2(SC2_, SC2_);
    int g = lane >> 2, q2 = lane & 3;

    for (int u = u0; u < u1; u++) {
        int ih = u >> 6, t = u & 63;
        int h = ih & 7, i = ih >> 3;
        int p = (u - u0) & 1;

        if (ih != curih) {
            unsigned* z = (unsigned*)smem;
            for (int idx = tid; idx < (MR_*SA_)/2; idx += NT_) z[idx] = 0u;
            __syncthreads();
            const float* Qg = g_query + (size_t)ih*(Q_*D_);
            unsigned char* A = smem;
            for (int idx = tid; idx < (Q_*D_)/2; idx += NT_) {
                int q = idx >> 5, d2 = (idx & 31)*2;
                float2 x = *(const float2*)&Qg[q*64 + d2];
                __nv_bfloat162 hi = __floats2bfloat162_rn(x.x, x.y);
                float2 hf = __bfloat1622float2(hi);
                __nv_bfloat162 lo = __floats2bfloat162_rn(x.x - hf.x, x.y - hf.y);
                *(__nv_bfloat162*)(A + (q*SA_ + d2)*2)       = hi;
                *(__nv_bfloat162*)(A + (q*SA_ + 64 + d2)*2)  = hi;
                *(__nv_bfloat162*)(A + (q*SA_ + 128 + d2)*2) = lo;
            }
            __syncthreads();
            if (wid < 13) {
                int lrow = lane & 15;
                int lcol = (lane < 16) ? 0 : 8;
                #pragma unroll
                for (int ks = 0; ks < 12; ks++) {
                    unsigned a = sbase + (unsigned)(((wid*16 + lrow)*SA_ + ks*16 + lcol)*2);
                    ldm_x4(a, af[ks][0], af[ks][1], af[ks][2], af[ks][3]);
                }
            }
            curih = ih;
        }

        long long tileOff = ((long long)(i*T_ + t)*H_ + h) * (Q_*K_);
        ull e0[4], e1[4];
        int r0 = wid*16 + g;
        unsigned yoT = sbase + YO_OFF + (unsigned)(t*128);

        // ---- phase 1: MMA+exp+attn-store+partials (warps 0-12); cp.async prefetch (13-15) ----
        if (wid < 13) {
            unsigned sBb = sbase + B_OFF + (unsigned)(p*BBUF);
            int ln = lane & 15;
            int bn = ln & 7;
            int bc = (ln < 8) ? 0 : 8;
            float c[4][4] = {};
            #pragma unroll
            for (int ks = 0; ks < 12; ks++) {
                unsigned b0[4], b1[4];
                #pragma unroll
                for (int nt = 0; nt < 4; nt++) {
                    unsigned a = sBb + (unsigned)(((nt*8 + bn)*SA_ + ks*16 + bc)*2);
                    ldm_x2(a, b0[nt], b1[nt]);
                }
                #pragma unroll
                for (int nt = 0; nt < 4; nt++)
                    mma_bf16(c[nt], af[ks][0], af[ks][1], af[ks][2], af[ks][3], b0[nt], b1[nt]);
            }
            ull rs0 = pack2(0.f, 0.f), rs1 = pack2(0.f, 0.f);
            #pragma unroll
            for (int nt = 0; nt < 4; nt++) {
                ull yo = lds1(yoT + (unsigned)((nt*8 + 2*q2)*4));
                ull v0 = fma2(pack2(c[nt][0], c[nt][1]), S2, yo);
                ull v1 = fma2(pack2(c[nt][2], c[nt][3]), S2, yo);
                e0[nt] = pack2(ex2(lo2(v0)), ex2(hi2(v0)));
                e1[nt] = pack2(ex2(lo2(v1)), ex2(hi2(v1)));
                rs0 = add2(rs0, e0[nt]);
                rs1 = add2(rs1, e1[nt]);
            }
            float rsum0 = lo2(rs0) + hi2(rs0);
            float rsum1 = lo2(rs1) + hi2(rs1);
            rsum0 += __shfl_xor_sync(0xffffffffu, rsum0, 1);
            rsum0 += __shfl_xor_sync(0xffffffffu, rsum0, 2);
            rsum1 += __shfl_xor_sync(0xffffffffu, rsum1, 1);
            rsum1 += __shfl_xor_sync(0xffffffffu, rsum1, 2);
            float rinv0 = rcpa(rsum0), rinv1 = rcpa(rsum1);
            if (wAttn) {
                float* ap = out + OUT_N + tileOff;
                ull rv0 = pack2(rinv0, rinv0), rv1 = pack2(rinv1, rinv1);
                if (r0 < Q_) {
                    #pragma unroll
                    for (int nt = 0; nt < 4; nt++)
                        stg2(ap + r0*K_ + nt*8 + 2*q2, mul2(e0[nt], rv0));
                }
                if (r0 + 8 < Q_) {
                    #pragma unroll
                    for (int nt = 0; nt < 4; nt++)
                        stg2(ap + (r0 + 8)*K_ + nt*8 + 2*q2, mul2(e1[nt], rv1));
                }
            }
            float m0f = (r0 < Q_) ? 1.f : 0.f;
            float m1f = (r0 + 8 < Q_) ? 1.f : 0.f;
            ull M0 = pack2(m0f, m0f), M1 = pack2(m1f, m1f);
            ull rv0p = pack2(rinv0*m0f, rinv0*m0f);
            ull rv1p = pack2(rinv1*m1f, rinv1*m1f);
            #pragma unroll
            for (int nt = 0; nt < 4; nt++) {
                ull pe = fma2(e1[nt], M1, mul2(e0[nt], M0));
                ull pa = fma2(e1[nt], rv1p, mul2(e0[nt], rv0p));
                float pex = lo2(pe), pey = hi2(pe), pax = lo2(pa), pay = hi2(pa);
                #pragma unroll
                for (int o = 4; o <= 16; o <<= 1) {
                    pex += __shfl_xor_sync(0xffffffffu, pex, o);
                    pey += __shfl_xor_sync(0xffffffffu, pey, o);
                    pax += __shfl_xor_sync(0xffffffffu, pax, o);
                    pay += __shfl_xor_sync(0xffffffffu, pay, o);
                }
                if (lane < 4) {
                    int col = nt*8 + 2*lane;
                    sPE[wid*32 + col] = pex; sPE[wid*32 + col + 1] = pey;
                    sPA[wid*32 + col] = pax; sPA[wid*32 + col + 1] = pay;
                }
            }
        } else if (u + 1 < u1) {
            // async prefetch of unit u+1 (non-blocking)
            int un = u + 1, ihn = un >> 6, tn = un & 63, hn = ihn & 7;
            int pn = p ^ 1;
            int idx0 = tid - 416;
            const unsigned char* bs = g_kb + (size_t)(tn*H_ + hn)*BBUF;
            unsigned bd = sbase + B_OFF + (unsigned)(pn*BBUF);
            for (int idx = idx0; idx < BBUF/16; idx += 96)
                cpa16(bd + idx*16, bs + idx*16);
            const unsigned char* vs = (const unsigned char*)(g_value + (size_t)(tn*H_ + hn)*(K_*D_));
            unsigned vd = sbase + V_OFF + (unsigned)(pn*VBUF);
            for (int idx = idx0; idx < VBUF/16; idx += 96)
                cpa16(vd + idx*16, vs + idx*16);
            CPA_COMMIT();
        }
        __syncthreads();

        // ---- phase 2 (merged): colsums + text + pooled ----
        float pe = 0.f, pa = 0.f;
        {
            #pragma unroll
            for (int w = 0; w < 13; w++) {
                pe += sPE[w*32 + lane];
                pa += sPA[w*32 + lane];
            }
        }
        float yv = sYO[t*K_ + lane];
        float ta = (yv == 0.f) ? rcpa(pe) : 0.f;
        float tb = (yv == 0.f) ? 0.f : (1.f / (float)Q_);

        if (wText && wid < 13) {
            float* tbase = out + OUT_N + (long long)ATT_N + tileOff;
            #pragma unroll
            for (int nt = 0; nt < 4; nt++) {
                int col = nt*8 + 2*q2;
                float tax = __shfl_sync(0xffffffffu, ta, col);
                float tay = __shfl_sync(0xffffffffu, ta, col + 1);
                float tbx = __shfl_sync(0xffffffffu, tb, col);
                float tby = __shfl_sync(0xffffffffu, tb, col + 1);
                ull ta2 = pack2(tax, tay), tb2 = pack2(tbx, tby);
                if (r0 < Q_)     stg2(tbase + r0*K_ + col,       fma2(e0[nt], ta2, tb2));
                if (r0 + 8 < Q_) stg2(tbase + (r0 + 8)*K_ + col, fma2(e1[nt], ta2, tb2));
            }
        }
        if (wid == 13 || wid == 14) {
            int d = (wid - 13)*32 + lane;
            const float* vv = sV + p*(K_*D_);
            float a = 0.f;
            #pragma unroll
            for (int k = 0; k < 32; k++)
                a = fmaf(__shfl_sync(0xffffffffu, pa, k), vv[k*D_ + d], a);
            g_pooled[(long long)(i*T_ + t)*E_ + h*64 + d] = a * (1.f / (float)Q_);
        }
        CPA_WAIT();
        __syncthreads();
    }
}

__global__ void fc_kernel(const float* __restrict__ Wo, const float* __restrict__ bo,
                          float* __restrict__ out) {
    __shared__ float sA[64*33];
    __shared__ float sB[64*33];
    int rt = blockIdx.x * 64;
    int ct = blockIdx.y * 64;
    int tid = threadIdx.x;
    int tx = tid & 15, ty = tid >> 4;
    float acc[4][4] = {};
    float ra[8], rb[8];
    #pragma unroll
    for (int j = 0; j < 8; j++) {
        int idx = tid + j*256;
        int r = idx >> 5, kk = idx & 31;
        ra[j] = g_pooled[(rt + r)*E_ + kk];
        rb[j] = Wo[(ct + r)*E_ + kk];
    }
    for (int kc = 0; kc < E_; kc += 32) {
        #pragma unroll
        for (int j = 0; j < 8; j++) {
            int idx = tid + j*256;
            int r = idx >> 5, kk = idx & 31;
            sA[r*33 + kk] = ra[j];
            sB[r*33 + kk] = rb[j];
        }
        __syncthreads();
        if (kc + 32 < E_) {
            #pragma unroll
            for (int j = 0; j < 8; j++) {
                int idx = tid + j*256;
                int r = idx >> 5, kk = idx & 31;
                ra[j] = g_pooled[(rt + r)*E_ + kc + 32 + kk];
                rb[j] = Wo[(ct + r)*E_ + kc + 32 + kk];
            }
        }
        #pragma unroll
        for (int kk = 0; kk < 32; kk++) {
            float a[4], b[4];
            #pragma unroll
            for (int r = 0; r < 4; r++) a[r] = sA[(ty*4 + r)*33 + kk];
            #pragma unroll
            for (int c = 0; c < 4; c++) b[c] = sB[(tx*4 + c)*33 + kk];
            #pragma unroll
            for (int r = 0; r < 4; r++)
                #pragma unroll
                for (int c = 0; c < 4; c++) acc[r][c] += a[r] * b[c];
        }
        __syncthreads();
    }
    #pragma unroll
    for (int r = 0; r < 4; r++)
        #pragma unroll
        for (int c = 0; c < 4; c++)
            out[(rt + ty*4 + r)*E_ + ct + tx*4 + c] = acc[r][c] + bo[ct + tx*4 + c];
}

extern "C" void kernel_launch(void* const* d_in, const int* in_sizes, int n_in,
                              void* d_out, int out_size) {
    const float* image = (const float*)d_in[0];
    const float* text  = (const float*)d_in[1];
    const void*  mask  =                d_in[2];
    const float* Wq    = (const float*)d_in[3];
    const float* Wk    = (const float*)d_in[4];
    const float* Wv    = (const float*)d_in[5];
    const float* Wo    = (const float*)d_in[6];
    const float* bo    = (const float*)d_in[7];
    float* out = (float*)d_out;

    cudaFuncSetAttribute(attn_kernel, cudaFuncAttributeMaxDynamicSharedMemorySize, SMEM_ATTN);

    mask_kernel<<<1, 256>>>(mask);
    proj_all<<<904, 256>>>(image, text, Wq, Wk, Wv);
    kprep_kernel<<<T_*H_, 256>>>();

    int wAttn = out_size >= (OUT_N + ATT_N);
    int wText = out_size >= (OUT_N + 2*ATT_N);
    attn_kernel<<<NCTA_, NT_, SMEM_ATTN>>>(out, wAttn, wText);

    if (out_size >= OUT_N)
        fc_kernel<<<dim3(16, 8), 256>>>(Wo, bo, out);
}